// round 3
// baseline (speedup 1.0000x reference)
#include <cuda_runtime.h>
#include <math.h>

// Problem constants (fixed by the reference)
constexpr int B  = 4;
constexpr int S  = 1024;
constexpr int D  = 1024;
constexpr int H  = 16;
constexpr int DKH = 64;            // key_size == head_size
constexpr int M  = B * S;          // 4096 rows
constexpr int NN = H * DKH;        // 1024 cols
constexpr int KK = D;              // 1024 reduction

// Scratch (device globals: allocation-free)
__device__ float g_qw[(size_t)M * NN];
__device__ float g_kw[(size_t)M * NN];
__device__ float g_vw[(size_t)M * NN];
__device__ float g_at[(size_t)M * NN];

// ---------------------------------------------------------------------------
// GEMM body: Y[M,NN] = X[M,KK] @ W[KK,NN] + bias, optionally * rowmask[row]
// 128x128 block tile, BK=16, 256 threads, 8x8 per-thread, smem double buffer.
// ---------------------------------------------------------------------------
__device__ __forceinline__ void gemm_body(
    const float* __restrict__ X, const float* __restrict__ W,
    const float* __restrict__ bias, float* __restrict__ Y,
    const int* __restrict__ rmask)
{
    __shared__ __align__(16) float As[2][16][128];
    __shared__ __align__(16) float Bs[2][16][128];

    const int tid = threadIdx.x;
    const int tx  = tid & 15;       // 0..15  (N direction)
    const int ty  = tid >> 4;       // 0..15  (M direction)
    const int bm  = blockIdx.y * 128;
    const int bn  = blockIdx.x * 128;

    // global load mapping
    const int ar = tid >> 1;            // 0..127 (A row within tile)
    const int ac = (tid & 1) << 3;      // 0 or 8 (A col within k-tile)
    const int br = tid >> 4;            // 0..15  (B row within k-tile)
    const int bc = (tid & 15) << 3;     // 0..120 (B col within tile)

    const float* Aptr = X + (size_t)(bm + ar) * KK + ac;
    const float* Bptr = W + (size_t)br * NN + bn + bc;

    float acc[8][8];
#pragma unroll
    for (int i = 0; i < 8; i++)
#pragma unroll
        for (int j = 0; j < 8; j++) acc[i][j] = 0.f;

    // prologue: tile 0 -> buf 0
    {
        float4 x0 = *(const float4*)(Aptr);
        float4 x1 = *(const float4*)(Aptr + 4);
        As[0][ac + 0][ar] = x0.x; As[0][ac + 1][ar] = x0.y;
        As[0][ac + 2][ar] = x0.z; As[0][ac + 3][ar] = x0.w;
        As[0][ac + 4][ar] = x1.x; As[0][ac + 5][ar] = x1.y;
        As[0][ac + 6][ar] = x1.z; As[0][ac + 7][ar] = x1.w;
        *(float4*)&Bs[0][br][bc]     = *(const float4*)(Bptr);
        *(float4*)&Bs[0][br][bc + 4] = *(const float4*)(Bptr + 4);
    }
    __syncthreads();

    int buf = 0;
    const int NT = KK >> 4;     // 64 k-tiles
    for (int t = 0; t < NT; ++t) {
        float4 x0, x1, y0, y1;
        const bool has = (t + 1 < NT);
        if (has) {
            const float* Ap = Aptr + (t + 1) * 16;
            x0 = *(const float4*)Ap;
            x1 = *(const float4*)(Ap + 4);
            const float* Bp = Bptr + (size_t)(t + 1) * 16 * NN;
            y0 = *(const float4*)Bp;
            y1 = *(const float4*)(Bp + 4);
        }
#pragma unroll
        for (int kk = 0; kk < 16; ++kk) {
            float a[8], bb[8];
            *(float4*)&a[0]  = *(const float4*)&As[buf][kk][ty * 8];
            *(float4*)&a[4]  = *(const float4*)&As[buf][kk][ty * 8 + 4];
            *(float4*)&bb[0] = *(const float4*)&Bs[buf][kk][tx * 8];
            *(float4*)&bb[4] = *(const float4*)&Bs[buf][kk][tx * 8 + 4];
#pragma unroll
            for (int i = 0; i < 8; i++)
#pragma unroll
                for (int j = 0; j < 8; j++)
                    acc[i][j] += a[i] * bb[j];
        }
        if (has) {
            const int nb = buf ^ 1;
            As[nb][ac + 0][ar] = x0.x; As[nb][ac + 1][ar] = x0.y;
            As[nb][ac + 2][ar] = x0.z; As[nb][ac + 3][ar] = x0.w;
            As[nb][ac + 4][ar] = x1.x; As[nb][ac + 5][ar] = x1.y;
            As[nb][ac + 6][ar] = x1.z; As[nb][ac + 7][ar] = x1.w;
            *(float4*)&Bs[nb][br][bc]     = y0;
            *(float4*)&Bs[nb][br][bc + 4] = y1;
            __syncthreads();
            buf = nb;
        }
    }

    // epilogue: bias add (+ optional row mask), vectorized store
    float bl[8];
    *(float4*)&bl[0] = *(const float4*)(bias + bn + tx * 8);
    *(float4*)&bl[4] = *(const float4*)(bias + bn + tx * 8 + 4);
#pragma unroll
    for (int i = 0; i < 8; i++) {
        const int row = bm + ty * 8 + i;
        const float sc = rmask ? (float)rmask[row] : 1.0f;
        float4 r0, r1;
        r0.x = (acc[i][0] + bl[0]) * sc;
        r0.y = (acc[i][1] + bl[1]) * sc;
        r0.z = (acc[i][2] + bl[2]) * sc;
        r0.w = (acc[i][3] + bl[3]) * sc;
        r1.x = (acc[i][4] + bl[4]) * sc;
        r1.y = (acc[i][5] + bl[5]) * sc;
        r1.z = (acc[i][6] + bl[6]) * sc;
        r1.w = (acc[i][7] + bl[7]) * sc;
        float* yp = Y + (size_t)row * NN + bn + tx * 8;
        *(float4*)yp       = r0;
        *(float4*)(yp + 4) = r1;
    }
}

__global__ __launch_bounds__(256, 2)
void gemm_qkv_kernel(const float* q, const float* k, const float* v,
                     const float* Wq, const float* bq,
                     const float* Wk, const float* bk,
                     const float* Wv, const float* bv)
{
    const float* X; const float* W; const float* bias; float* Y;
    if (blockIdx.z == 0)      { X = q; W = Wq; bias = bq; Y = g_qw; }
    else if (blockIdx.z == 1) { X = k; W = Wk; bias = bk; Y = g_kw; }
    else                      { X = v; W = Wv; bias = bv; Y = g_vw; }
    gemm_body(X, W, bias, Y, nullptr);
}

__global__ __launch_bounds__(256, 2)
void gemm_out_kernel(const float* Wo, const float* bo, float* out,
                     const int* qmask)
{
    gemm_body(g_at, Wo, bo, out, qmask);
}

// ---------------------------------------------------------------------------
// Flash attention per (b, h), 64 q-rows per CTA, streaming 64-key tiles.
// Reproduces the reference's fp32 additive -1e12 masking semantics exactly
// (including the "fully v-masked causal window attends future unmasked keys"
// quirk). Early-exits above the diagonal once no row is still fully masked.
// Static smem = exactly 48KB: Q[64x64], KP[64x64] (K^T then reused for P),
// V[64x64].
// ---------------------------------------------------------------------------
__global__ __launch_bounds__(256, 2)
void flash_kernel(const int* __restrict__ v_mask)
{
    __shared__ __align__(16) float Qs[64 * 64];
    __shared__ __align__(16) float KP[64 * 64];   // K^T (d-major), reused as P
    __shared__ __align__(16) float Vs[64 * 64];

    const int tid = threadIdx.x;
    const int tx  = tid & 15;
    const int ty  = tid >> 4;
    const int tx4 = tx * 4;
    const int ty4 = ty * 4;

    const int bh = blockIdx.y;
    const int b  = bh >> 4;
    const int h  = bh & 15;
    const int q0 = blockIdx.x * 64;
    const int hc = h * 64;

    // Load Q tile: Qs[r][d]
    {
        const int r  = tid >> 2;
        const int c0 = (tid & 3) << 4;
        const float* src = g_qw + (size_t)(b * S + q0 + r) * NN + hc + c0;
#pragma unroll
        for (int i = 0; i < 4; i++)
            *(float4*)&Qs[r * 64 + c0 + i * 4] = *(const float4*)(src + i * 4);
    }

    float m[4], l[4], o[4][4];
#pragma unroll
    for (int i = 0; i < 4; i++) {
        m[i] = -__int_as_float(0x7f800000);   // -inf
        l[i] = 0.f;
#pragma unroll
        for (int j = 0; j < 4; j++) o[i][j] = 0.f;
    }

    const int diag = blockIdx.x;
    const int nt   = S / 64;

    for (int t = 0; t < nt; ++t) {
        __syncthreads();   // previous iteration's KP/Vs reads complete
        // Load K (transposed) and V tiles
        {
            const int r  = tid >> 2;
            const int c0 = (tid & 3) << 4;
            const size_t base = (size_t)(b * S + t * 64 + r) * NN + hc + c0;
            const float* ks = g_kw + base;
            const float* vs = g_vw + base;
#pragma unroll
            for (int i = 0; i < 4; i++) {
                float4 kv = *(const float4*)(ks + i * 4);
                KP[(c0 + i * 4 + 0) * 64 + r] = kv.x;
                KP[(c0 + i * 4 + 1) * 64 + r] = kv.y;
                KP[(c0 + i * 4 + 2) * 64 + r] = kv.z;
                KP[(c0 + i * 4 + 3) * 64 + r] = kv.w;
                *(float4*)&Vs[r * 64 + c0 + i * 4] = *(const float4*)(vs + i * 4);
            }
        }
        // v_mask additive penalty for my 4 key columns (registers)
        float vmadd[4];
#pragma unroll
        for (int j = 0; j < 4; j++)
            vmadd[j] = (1.0f - (float)v_mask[b * S + t * 64 + tx4 + j]) * 1e12f;
        __syncthreads();

        // S = Q K^T
        float acc[4][4];
#pragma unroll
        for (int i = 0; i < 4; i++)
#pragma unroll
            for (int j = 0; j < 4; j++) acc[i][j] = 0.f;
#pragma unroll 8
        for (int d = 0; d < 64; ++d) {
            const float a0 = Qs[(ty4 + 0) * 64 + d];
            const float a1 = Qs[(ty4 + 1) * 64 + d];
            const float a2 = Qs[(ty4 + 2) * 64 + d];
            const float a3 = Qs[(ty4 + 3) * 64 + d];
            const float4 kv = *(const float4*)&KP[d * 64 + tx4];
            acc[0][0] += a0 * kv.x; acc[0][1] += a0 * kv.y;
            acc[0][2] += a0 * kv.z; acc[0][3] += a0 * kv.w;
            acc[1][0] += a1 * kv.x; acc[1][1] += a1 * kv.y;
            acc[1][2] += a1 * kv.z; acc[1][3] += a1 * kv.w;
            acc[2][0] += a2 * kv.x; acc[2][1] += a2 * kv.y;
            acc[2][2] += a2 * kv.z; acc[2][3] += a2 * kv.w;
            acc[3][0] += a3 * kv.x; acc[3][1] += a3 * kv.y;
            acc[3][2] += a3 * kv.z; acc[3][3] += a3 * kv.w;
        }
        __syncthreads();   // all KP (K^T) reads done before P overwrites it

        // masking + online softmax (fp32 arithmetic identical to reference)
#pragma unroll
        for (int i = 0; i < 4; i++) {
            const int qrow = q0 + ty4 + i;
            float sv[4];
            float rm = -__int_as_float(0x7f800000);
#pragma unroll
            for (int j = 0; j < 4; j++) {
                const int kcol = t * 64 + tx4 + j;
                float s = acc[i][j] * 0.125f;   // / sqrt(64)
                s = s - vmadd[j];               // sequence mask (add -1e12)
                if (kcol > qrow) s = s - 1e12f; // causal mask (add -1e12)
                sv[j] = s;
                rm = fmaxf(rm, s);
            }
#pragma unroll
            for (int off = 8; off; off >>= 1)
                rm = fmaxf(rm, __shfl_xor_sync(0xffffffffu, rm, off, 16));
            const float mn    = fmaxf(m[i], rm);
            const float alpha = expf(m[i] - mn);
            float rs = 0.f;
#pragma unroll
            for (int j = 0; j < 4; j++) {
                const float p = expf(sv[j] - mn);
                sv[j] = p;
                rs += p;
            }
#pragma unroll
            for (int off = 8; off; off >>= 1)
                rs += __shfl_xor_sync(0xffffffffu, rs, off, 16);
            l[i] = l[i] * alpha + rs;
            m[i] = mn;
#pragma unroll
            for (int j = 0; j < 4; j++) o[i][j] *= alpha;
#pragma unroll
            for (int j = 0; j < 4; j++)
                KP[(ty4 + i) * 64 + tx4 + j] = sv[j];   // P tile into KP
        }
        __syncthreads();

        // O += P V
#pragma unroll 16
        for (int k = 0; k < 64; ++k) {
            const float p0 = KP[(ty4 + 0) * 64 + k];
            const float p1 = KP[(ty4 + 1) * 64 + k];
            const float p2 = KP[(ty4 + 2) * 64 + k];
            const float p3 = KP[(ty4 + 3) * 64 + k];
            const float4 vv = *(const float4*)&Vs[k * 64 + tx4];
            o[0][0] += p0 * vv.x; o[0][1] += p0 * vv.y;
            o[0][2] += p0 * vv.z; o[0][3] += p0 * vv.w;
            o[1][0] += p1 * vv.x; o[1][1] += p1 * vv.y;
            o[1][2] += p1 * vv.z; o[1][3] += p1 * vv.w;
            o[2][0] += p2 * vv.x; o[2][1] += p2 * vv.y;
            o[2][2] += p2 * vv.z; o[2][3] += p2 * vv.w;
            o[3][0] += p3 * vv.x; o[3][1] += p3 * vv.y;
            o[3][2] += p3 * vv.z; o[3][3] += p3 * vv.w;
        }

        // Past the diagonal: continue only while some row is still fully
        // masked (its max is at the -1e12 level) — those rows legitimately
        // pick up future unmasked keys in the reference semantics.
        if (t >= diag) {
            int pred = 0;
#pragma unroll
            for (int i = 0; i < 4; i++) pred |= (m[i] <= -1e11f);
            if (!__syncthreads_or(pred)) break;
        }
    }

    // normalize + store
#pragma unroll
    for (int i = 0; i < 4; i++) {
        const float inv = 1.0f / l[i];
        float4 r;
        r.x = o[i][0] * inv;
        r.y = o[i][1] * inv;
        r.z = o[i][2] * inv;
        r.w = o[i][3] * inv;
        *(float4*)&g_at[(size_t)(b * S + q0 + ty4 + i) * NN + hc + tx4] = r;
    }
}

// ---------------------------------------------------------------------------
extern "C" void kernel_launch(void* const* d_in, const int* in_sizes, int n_in,
                              void* d_out, int out_size)
{
    (void)in_sizes; (void)n_in; (void)out_size;
    const float* q     = (const float*)d_in[0];
    const float* k     = (const float*)d_in[1];
    const float* v     = (const float*)d_in[2];
    const int*   vmask = (const int*)  d_in[3];
    const int*   qmask = (const int*)  d_in[4];
    // d_in[5] = a_mask (causal tril) — applied analytically in flash_kernel
    const float* Wq = (const float*)d_in[6];
    const float* bq = (const float*)d_in[7];
    const float* Wk = (const float*)d_in[8];
    const float* bk = (const float*)d_in[9];
    const float* Wv = (const float*)d_in[10];
    const float* bv = (const float*)d_in[11];
    const float* Wo = (const float*)d_in[12];
    const float* bo = (const float*)d_in[13];
    float* out = (float*)d_out;

    dim3 blk(256);
    gemm_qkv_kernel<<<dim3(NN / 128, M / 128, 3), blk>>>(q, k, v,
                                                         Wq, bq, Wk, bk, Wv, bv);
    flash_kernel<<<dim3(S / 64, B * H), blk>>>(vmask);
    gemm_out_kernel<<<dim3(NN / 128, M / 128), blk>>>(Wo, bo, out, qmask);
}

// round 6
// speedup vs baseline: 1.4719x; 1.4719x over previous
#include <cuda_runtime.h>
#include <cuda_bf16.h>
#include <math.h>
#include <stdint.h>

// Problem constants
constexpr int B  = 4;
constexpr int S  = 1024;
constexpr int H  = 16;
constexpr int M  = B * S;          // 4096
constexpr int NN = H * 64;         // 1024
constexpr int KK = 1024;

// Scratch (device globals: allocation-free)
__device__ float g_qw[(size_t)M * NN];
__device__ float g_kw[(size_t)M * NN];
__device__ float g_vw[(size_t)M * NN];
__device__ float g_at[(size_t)M * NN];

// ===========================================================================
// Helpers
// ===========================================================================
__device__ __forceinline__ uint32_t smem_u32(const void* p) {
    uint32_t a;
    asm("{ .reg .u64 t; cvta.to.shared.u64 t, %1; cvt.u32.u64 %0, t; }"
        : "=r"(a) : "l"(p));
    return a;
}
__device__ __forceinline__ uint32_t pk2(float a, float b) {
    __nv_bfloat162 t;
    t.x = __float2bfloat16(a);
    t.y = __float2bfloat16(b);
    return *(uint32_t*)&t;
}
__device__ __forceinline__ float bres(float x) {   // residual after bf16 hi
    __nv_bfloat16 h = __float2bfloat16(x);
    return x - __bfloat162float(h);
}

// smem tile rows are 64B (32 bf16). Swizzle 16B chunks so that ldmatrix's
// 8-address phases and the converting stores are bank-conflict free.
__device__ __forceinline__ int sw_off(int row, int chunk) {
    return row * 64 + ((chunk ^ ((row >> 1) & 3) ^ ((row >> 3) & 3)) << 4);
}

#define LDMX4(r, addr) \
    asm volatile("ldmatrix.sync.aligned.m8n8.x4.shared.b16 {%0,%1,%2,%3}, [%4];" \
        : "=r"((r)[0]), "=r"((r)[1]), "=r"((r)[2]), "=r"((r)[3]) : "r"(addr))

#define MMA_BF16(d, a, bb) \
    asm volatile("mma.sync.aligned.m16n8k16.row.col.f32.bf16.bf16.f32 " \
        "{%0,%1,%2,%3}, {%4,%5,%6,%7}, {%8,%9}, {%0,%1,%2,%3};" \
        : "+f"((d)[0]), "+f"((d)[1]), "+f"((d)[2]), "+f"((d)[3]) \
        : "r"((a)[0]), "r"((a)[1]), "r"((a)[2]), "r"((a)[3]), \
          "r"((bb)[0]), "r"((bb)[1]))

// ===========================================================================
// mma.sync bf16 split GEMM: Y = X[M,K] @ W[K,N] + bias (optionally * rmask)
// Block 128(M) x 64(N), BK=32, 256 threads (8 warps, 4m x 2n, warp 32x32).
// Static smem = 48KB exactly (2 stages x 24KB). 3-pass hi/lo bf16 split.
// ===========================================================================
constexpr int BM = 128, BN = 64, BK = 32;
constexpr int STGB = 24576;                 // bytes per stage
constexpr int AHI = 0, ALO = 8192, BHI = 16384, BLO = 20480;
constexpr int NT = KK / BK;                 // 32 k-tiles

__device__ __forceinline__ void load_regs(const float* __restrict__ X,
                                          const float* __restrict__ W,
                                          int bm, int bn, int k0, int tid,
                                          float4* av, float* bv)
{
#pragma unroll
    for (int p = 0; p < 4; ++p) {
        const int idx = tid + p * 256;
        av[p] = *(const float4*)(X + (size_t)(bm + (idx >> 3)) * KK
                                 + k0 + (idx & 7) * 4);
    }
    const int n = tid & 63, q = tid >> 6;
    const float* wp = W + (size_t)(k0 + q * 8) * NN + bn + n;
#pragma unroll
    for (int j = 0; j < 8; ++j) bv[j] = wp[(size_t)j * NN];
}

__device__ __forceinline__ void store_stage(char* stg, int tid,
                                            const float4* av, const float* bv)
{
#pragma unroll
    for (int p = 0; p < 4; ++p) {
        const int idx = tid + p * 256;
        const int row = idx >> 3, f4 = idx & 7;
        uint2 hi, lo;
        hi.x = pk2(av[p].x, av[p].y);
        hi.y = pk2(av[p].z, av[p].w);
        lo.x = pk2(bres(av[p].x), bres(av[p].y));
        lo.y = pk2(bres(av[p].z), bres(av[p].w));
        const int off = sw_off(row, f4 >> 1) + (f4 & 1) * 8;
        *(uint2*)(stg + AHI + off) = hi;
        *(uint2*)(stg + ALO + off) = lo;
    }
    const int n = tid & 63, q = tid >> 6;
    uint4 hi, lo;
    hi.x = pk2(bv[0], bv[1]);  hi.y = pk2(bv[2], bv[3]);
    hi.z = pk2(bv[4], bv[5]);  hi.w = pk2(bv[6], bv[7]);
    lo.x = pk2(bres(bv[0]), bres(bv[1]));
    lo.y = pk2(bres(bv[2]), bres(bv[3]));
    lo.z = pk2(bres(bv[4]), bres(bv[5]));
    lo.w = pk2(bres(bv[6]), bres(bv[7]));
    const int off = sw_off(n, q);
    *(uint4*)(stg + BHI + off) = hi;
    *(uint4*)(stg + BLO + off) = lo;
}

__device__ __forceinline__ void mma_gemm_body(const float* __restrict__ X,
                                              const float* __restrict__ W,
                                              const float* __restrict__ bias,
                                              float* __restrict__ Y,
                                              const int* __restrict__ rmask)
{
    __shared__ __align__(128) char sm[2 * STGB];   // 49152 B

    const int tid  = threadIdx.x;
    const int lane = tid & 31;
    const int w    = tid >> 5;
    const int m0   = (w >> 1) * 32;
    const int n0   = (w & 1) * 32;
    const int bm   = blockIdx.y * BM;
    const int bn   = blockIdx.x * BN;
    const uint32_t sbase = smem_u32(sm);

    float acc[2][4][4];
#pragma unroll
    for (int mt = 0; mt < 2; ++mt)
#pragma unroll
        for (int nt = 0; nt < 4; ++nt)
#pragma unroll
            for (int i = 0; i < 4; ++i) acc[mt][nt][i] = 0.f;

    // prologue: tile 0 -> stage 0
    {
        float4 av[4]; float bv[8];
        load_regs(X, W, bm, bn, 0, tid, av, bv);
        store_stage(sm, tid, av, bv);
    }
    __syncthreads();

    for (int t = 0; t < NT; ++t) {
        const int cur = t & 1;
        float4 av[4]; float bv[8];
        const bool pf = (t + 1 < NT);
        if (pf) load_regs(X, W, bm, bn, (t + 1) * BK, tid, av, bv);

        const uint32_t sA = sbase + cur * STGB;
        const uint32_t sB = sA + BHI;
#pragma unroll
        for (int ks = 0; ks < 2; ++ks) {
            uint32_t ah[2][4], al[2][4], bh[4][2], bl[4][2];
#pragma unroll
            for (int mt = 0; mt < 2; ++mt) {
                const int row = m0 + mt * 16 + (lane & 15);
                const int ch  = ks * 2 + (lane >> 4);
                const uint32_t ad = sA + sw_off(row, ch);
                LDMX4(ah[mt], ad);
                LDMX4(al[mt], ad + ALO);
            }
#pragma unroll
            for (int np = 0; np < 2; ++np) {
                const int nr = n0 + np * 16 + ((lane >> 4) << 3) + (lane & 7);
                const int ch = ks * 2 + ((lane >> 3) & 1);
                const uint32_t ad = sB + sw_off(nr, ch);
                uint32_t th[4], tl[4];
                LDMX4(th, ad);
                LDMX4(tl, ad + (BLO - BHI));
                bh[np * 2][0] = th[0]; bh[np * 2][1] = th[1];
                bh[np * 2 + 1][0] = th[2]; bh[np * 2 + 1][1] = th[3];
                bl[np * 2][0] = tl[0]; bl[np * 2][1] = tl[1];
                bl[np * 2 + 1][0] = tl[2]; bl[np * 2 + 1][1] = tl[3];
            }
#pragma unroll
            for (int mt = 0; mt < 2; ++mt)
#pragma unroll
                for (int nt = 0; nt < 4; ++nt) {
                    MMA_BF16(acc[mt][nt], ah[mt], bh[nt]);
                    MMA_BF16(acc[mt][nt], ah[mt], bl[nt]);
                    MMA_BF16(acc[mt][nt], al[mt], bh[nt]);
                }
        }
        if (pf) store_stage(sm + (cur ^ 1) * STGB, tid, av, bv);
        __syncthreads();
    }

    // epilogue: direct register->global, mma C-fragment layout
#pragma unroll
    for (int nt = 0; nt < 4; ++nt) {
        const int gc = bn + n0 + nt * 8 + (lane & 3) * 2;
        const float b0 = bias[gc], b1 = bias[gc + 1];
#pragma unroll
        for (int mt = 0; mt < 2; ++mt) {
            const int gr = bm + m0 + mt * 16 + (lane >> 2);
            const float s0 = rmask ? (float)rmask[gr] : 1.f;
            const float s1 = rmask ? (float)rmask[gr + 8] : 1.f;
            float2 v0, v1;
            v0.x = (acc[mt][nt][0] + b0) * s0;
            v0.y = (acc[mt][nt][1] + b1) * s0;
            v1.x = (acc[mt][nt][2] + b0) * s1;
            v1.y = (acc[mt][nt][3] + b1) * s1;
            *(float2*)(Y + (size_t)gr * NN + gc)       = v0;
            *(float2*)(Y + (size_t)(gr + 8) * NN + gc) = v1;
        }
    }
}

__global__ __launch_bounds__(256, 1)
void mma_gemm_qkv(const float* q, const float* k, const float* v,
                  const float* Wq, const float* bq,
                  const float* Wk, const float* bk,
                  const float* Wv, const float* bv)
{
    const float* X; const float* W; const float* bias; float* Y;
    if (blockIdx.z == 0)      { X = q; W = Wq; bias = bq; Y = g_qw; }
    else if (blockIdx.z == 1) { X = k; W = Wk; bias = bk; Y = g_kw; }
    else                      { X = v; W = Wv; bias = bv; Y = g_vw; }
    mma_gemm_body(X, W, bias, Y, nullptr);
}

__global__ __launch_bounds__(256, 1)
void mma_gemm_out(const float* Wo, const float* bo, float* out,
                  const int* qmask)
{
    mma_gemm_body(g_at, Wo, bo, out, qmask);
}

// ---------------------------------------------------------------------------
// Flash attention (unchanged — proven correct, exact reference masking
// semantics incl. the fully-v-masked-row "future keys" quirk).
// ---------------------------------------------------------------------------
__global__ __launch_bounds__(256, 2)
void flash_kernel(const int* __restrict__ v_mask)
{
    __shared__ __align__(16) float Qs[64 * 64];
    __shared__ __align__(16) float KP[64 * 64];
    __shared__ __align__(16) float Vs[64 * 64];

    const int tid = threadIdx.x;
    const int tx  = tid & 15;
    const int ty  = tid >> 4;
    const int tx4 = tx * 4;
    const int ty4 = ty * 4;

    const int bh = blockIdx.y;
    const int b  = bh >> 4;
    const int h  = bh & 15;
    const int q0 = blockIdx.x * 64;
    const int hc = h * 64;

    {
        const int r  = tid >> 2;
        const int c0 = (tid & 3) << 4;
        const float* src = g_qw + (size_t)(b * S + q0 + r) * NN + hc + c0;
#pragma unroll
        for (int i = 0; i < 4; i++)
            *(float4*)&Qs[r * 64 + c0 + i * 4] = *(const float4*)(src + i * 4);
    }

    float m[4], l[4], o[4][4];
#pragma unroll
    for (int i = 0; i < 4; i++) {
        m[i] = -__int_as_float(0x7f800000);
        l[i] = 0.f;
#pragma unroll
        for (int j = 0; j < 4; j++) o[i][j] = 0.f;
    }

    const int diag = blockIdx.x;
    const int nt   = S / 64;

    for (int t = 0; t < nt; ++t) {
        __syncthreads();
        {
            const int r  = tid >> 2;
            const int c0 = (tid & 3) << 4;
            const size_t base = (size_t)(b * S + t * 64 + r) * NN + hc + c0;
            const float* ks = g_kw + base;
            const float* vs = g_vw + base;
#pragma unroll
            for (int i = 0; i < 4; i++) {
                float4 kv = *(const float4*)(ks + i * 4);
                KP[(c0 + i * 4 + 0) * 64 + r] = kv.x;
                KP[(c0 + i * 4 + 1) * 64 + r] = kv.y;
                KP[(c0 + i * 4 + 2) * 64 + r] = kv.z;
                KP[(c0 + i * 4 + 3) * 64 + r] = kv.w;
                *(float4*)&Vs[r * 64 + c0 + i * 4] = *(const float4*)(vs + i * 4);
            }
        }
        float vmadd[4];
#pragma unroll
        for (int j = 0; j < 4; j++)
            vmadd[j] = (1.0f - (float)v_mask[b * S + t * 64 + tx4 + j]) * 1e12f;
        __syncthreads();

        float acc[4][4];
#pragma unroll
        for (int i = 0; i < 4; i++)
#pragma unroll
            for (int j = 0; j < 4; j++) acc[i][j] = 0.f;
#pragma unroll 8
        for (int d = 0; d < 64; ++d) {
            const float a0 = Qs[(ty4 + 0) * 64 + d];
            const float a1 = Qs[(ty4 + 1) * 64 + d];
            const float a2 = Qs[(ty4 + 2) * 64 + d];
            const float a3 = Qs[(ty4 + 3) * 64 + d];
            const float4 kv = *(const float4*)&KP[d * 64 + tx4];
            acc[0][0] += a0 * kv.x; acc[0][1] += a0 * kv.y;
            acc[0][2] += a0 * kv.z; acc[0][3] += a0 * kv.w;
            acc[1][0] += a1 * kv.x; acc[1][1] += a1 * kv.y;
            acc[1][2] += a1 * kv.z; acc[1][3] += a1 * kv.w;
            acc[2][0] += a2 * kv.x; acc[2][1] += a2 * kv.y;
            acc[2][2] += a2 * kv.z; acc[2][3] += a2 * kv.w;
            acc[3][0] += a3 * kv.x; acc[3][1] += a3 * kv.y;
            acc[3][2] += a3 * kv.z; acc[3][3] += a3 * kv.w;
        }
        __syncthreads();

#pragma unroll
        for (int i = 0; i < 4; i++) {
            const int qrow = q0 + ty4 + i;
            float sv[4];
            float rm = -__int_as_float(0x7f800000);
#pragma unroll
            for (int j = 0; j < 4; j++) {
                const int kcol = t * 64 + tx4 + j;
                float s = acc[i][j] * 0.125f;
                s = s - vmadd[j];
                if (kcol > qrow) s = s - 1e12f;
                sv[j] = s;
                rm = fmaxf(rm, s);
            }
#pragma unroll
            for (int off = 8; off; off >>= 1)
                rm = fmaxf(rm, __shfl_xor_sync(0xffffffffu, rm, off, 16));
            const float mn    = fmaxf(m[i], rm);
            const float alpha = expf(m[i] - mn);
            float rs = 0.f;
#pragma unroll
            for (int j = 0; j < 4; j++) {
                const float p = expf(sv[j] - mn);
                sv[j] = p;
                rs += p;
            }
#pragma unroll
            for (int off = 8; off; off >>= 1)
                rs += __shfl_xor_sync(0xffffffffu, rs, off, 16);
            l[i] = l[i] * alpha + rs;
            m[i] = mn;
#pragma unroll
            for (int j = 0; j < 4; j++) o[i][j] *= alpha;
#pragma unroll
            for (int j = 0; j < 4; j++)
                KP[(ty4 + i) * 64 + tx4 + j] = sv[j];
        }
        __syncthreads();

#pragma unroll 16
        for (int k = 0; k < 64; ++k) {
            const float p0 = KP[(ty4 + 0) * 64 + k];
            const float p1 = KP[(ty4 + 1) * 64 + k];
            const float p2 = KP[(ty4 + 2) * 64 + k];
            const float p3 = KP[(ty4 + 3) * 64 + k];
            const float4 vv = *(const float4*)&Vs[k * 64 + tx4];
            o[0][0] += p0 * vv.x; o[0][1] += p0 * vv.y;
            o[0][2] += p0 * vv.z; o[0][3] += p0 * vv.w;
            o[1][0] += p1 * vv.x; o[1][1] += p1 * vv.y;
            o[1][2] += p1 * vv.z; o[1][3] += p1 * vv.w;
            o[2][0] += p2 * vv.x; o[2][1] += p2 * vv.y;
            o[2][2] += p2 * vv.z; o[2][3] += p2 * vv.w;
            o[3][0] += p3 * vv.x; o[3][1] += p3 * vv.y;
            o[3][2] += p3 * vv.z; o[3][3] += p3 * vv.w;
        }

        if (t >= diag) {
            int pred = 0;
#pragma unroll
            for (int i = 0; i < 4; i++) pred |= (m[i] <= -1e11f);
            if (!__syncthreads_or(pred)) break;
        }
    }

#pragma unroll
    for (int i = 0; i < 4; i++) {
        const float inv = 1.0f / l[i];
        float4 r;
        r.x = o[i][0] * inv;
        r.y = o[i][1] * inv;
        r.z = o[i][2] * inv;
        r.w = o[i][3] * inv;
        *(float4*)&g_at[(size_t)(b * S + q0 + ty4 + i) * NN + hc + tx4] = r;
    }
}

// ---------------------------------------------------------------------------
extern "C" void kernel_launch(void* const* d_in, const int* in_sizes, int n_in,
                              void* d_out, int out_size)
{
    (void)in_sizes; (void)n_in; (void)out_size;
    const float* q     = (const float*)d_in[0];
    const float* k     = (const float*)d_in[1];
    const float* v     = (const float*)d_in[2];
    const int*   vmask = (const int*)  d_in[3];
    const int*   qmask = (const int*)  d_in[4];
    const float* Wq = (const float*)d_in[6];
    const float* bq = (const float*)d_in[7];
    const float* Wk = (const float*)d_in[8];
    const float* bk = (const float*)d_in[9];
    const float* Wv = (const float*)d_in[10];
    const float* bv = (const float*)d_in[11];
    const float* Wo = (const float*)d_in[12];
    const float* bo = (const float*)d_in[13];
    float* out = (float*)d_out;

    mma_gemm_qkv<<<dim3(NN / BN, M / BM, 3), 256>>>(q, k, v,
                                                    Wq, bq, Wk, bk, Wv, bv);
    flash_kernel<<<dim3(S / 64, B * H), 256>>>(vmask);
    mma_gemm_out<<<dim3(NN / BN, M / BM), 256>>>(Wo, bo, out, qmask);
}

// round 9
// speedup vs baseline: 2.3389x; 1.5890x over previous
#include <cuda_runtime.h>
#include <cuda_bf16.h>
#include <math.h>
#include <stdint.h>

// Problem constants
constexpr int B  = 4;
constexpr int S  = 1024;
constexpr int H  = 16;
constexpr int M  = B * S;          // 4096
constexpr int NN = H * 64;         // 1024
constexpr int KK = 1024;

// Scratch (device globals: allocation-free)
__device__ float g_qw[(size_t)M * NN];
__device__ float g_kw[(size_t)M * NN];
__device__ float g_vw[(size_t)M * NN];
__device__ float g_at[(size_t)M * NN];

// ===========================================================================
// Helpers
// ===========================================================================
__device__ __forceinline__ uint32_t smem_u32(const void* p) {
    uint32_t a;
    asm("{ .reg .u64 t; cvta.to.shared.u64 t, %1; cvt.u32.u64 %0, t; }"
        : "=r"(a) : "l"(p));
    return a;
}
__device__ __forceinline__ uint32_t pk2(float a, float b) {
    __nv_bfloat162 t;
    t.x = __float2bfloat16(a);
    t.y = __float2bfloat16(b);
    return *(uint32_t*)&t;
}
__device__ __forceinline__ float bres(float x) {   // residual after bf16 hi
    __nv_bfloat16 h = __float2bfloat16(x);
    return x - __bfloat162float(h);
}

// 64B-row swizzle (GEMM tiles: 32 bf16 per row)
__device__ __forceinline__ int sw_off(int row, int chunk) {
    return row * 64 + ((chunk ^ ((row >> 1) & 3) ^ ((row >> 3) & 3)) << 4);
}
// 128B-row swizzle (flash tiles: 64 bf16 per row), chunk = 16B unit 0..7
__device__ __forceinline__ int fsw(int row, int chunk) {
    return row * 128 + ((chunk ^ (row & 7)) << 4);
}

#define LDMX4(r, addr) \
    asm volatile("ldmatrix.sync.aligned.m8n8.x4.shared.b16 {%0,%1,%2,%3}, [%4];" \
        : "=r"((r)[0]), "=r"((r)[1]), "=r"((r)[2]), "=r"((r)[3]) : "r"(addr))
#define LDMX4T(r, addr) \
    asm volatile("ldmatrix.sync.aligned.m8n8.x4.trans.shared.b16 {%0,%1,%2,%3}, [%4];" \
        : "=r"((r)[0]), "=r"((r)[1]), "=r"((r)[2]), "=r"((r)[3]) : "r"(addr))

#define MMA_BF16(d, a, bb) \
    asm volatile("mma.sync.aligned.m16n8k16.row.col.f32.bf16.bf16.f32 " \
        "{%0,%1,%2,%3}, {%4,%5,%6,%7}, {%8,%9}, {%0,%1,%2,%3};" \
        : "+f"((d)[0]), "+f"((d)[1]), "+f"((d)[2]), "+f"((d)[3]) \
        : "r"((a)[0]), "r"((a)[1]), "r"((a)[2]), "r"((a)[3]), \
          "r"((bb)[0]), "r"((bb)[1]))

// ===========================================================================
// mma.sync bf16 split GEMM: Y = X[M,K] @ W[K,N] + bias (optionally * rmask)
// Block 128(M) x 64(N), BK=32, 256 threads (8 warps, 4m x 2n, warp 32x32).
// Static smem = 48KB exactly (2 stages x 24KB). 3-pass hi/lo bf16 split.
// __launch_bounds__(256,2): <=128 regs -> 2 CTAs/SM.
// ===========================================================================
constexpr int BM = 128, BN = 64, BK = 32;
constexpr int STGB = 24576;
constexpr int AHI = 0, ALO = 8192, BHI = 16384, BLO = 20480;
constexpr int NT = KK / BK;

__device__ __forceinline__ void load_regs(const float* __restrict__ X,
                                          const float* __restrict__ W,
                                          int bm, int bn, int k0, int tid,
                                          float4* av, float* bv)
{
#pragma unroll
    for (int p = 0; p < 4; ++p) {
        const int idx = tid + p * 256;
        av[p] = *(const float4*)(X + (size_t)(bm + (idx >> 3)) * KK
                                 + k0 + (idx & 7) * 4);
    }
    const int n = tid & 63, q = tid >> 6;
    const float* wp = W + (size_t)(k0 + q * 8) * NN + bn + n;
#pragma unroll
    for (int j = 0; j < 8; ++j) bv[j] = wp[(size_t)j * NN];
}

__device__ __forceinline__ void store_stage(char* stg, int tid,
                                            const float4* av, const float* bv)
{
#pragma unroll
    for (int p = 0; p < 4; ++p) {
        const int idx = tid + p * 256;
        const int row = idx >> 3, f4 = idx & 7;
        uint2 hi, lo;
        hi.x = pk2(av[p].x, av[p].y);
        hi.y = pk2(av[p].z, av[p].w);
        lo.x = pk2(bres(av[p].x), bres(av[p].y));
        lo.y = pk2(bres(av[p].z), bres(av[p].w));
        const int off = sw_off(row, f4 >> 1) + (f4 & 1) * 8;
        *(uint2*)(stg + AHI + off) = hi;
        *(uint2*)(stg + ALO + off) = lo;
    }
    const int n = tid & 63, q = tid >> 6;
    uint4 hi, lo;
    hi.x = pk2(bv[0], bv[1]);  hi.y = pk2(bv[2], bv[3]);
    hi.z = pk2(bv[4], bv[5]);  hi.w = pk2(bv[6], bv[7]);
    lo.x = pk2(bres(bv[0]), bres(bv[1]));
    lo.y = pk2(bres(bv[2]), bres(bv[3]));
    lo.z = pk2(bres(bv[4]), bres(bv[5]));
    lo.w = pk2(bres(bv[6]), bres(bv[7]));
    const int off = sw_off(n, q);
    *(uint4*)(stg + BHI + off) = hi;
    *(uint4*)(stg + BLO + off) = lo;
}

__device__ __forceinline__ void mma_gemm_body(const float* __restrict__ X,
                                              const float* __restrict__ W,
                                              const float* __restrict__ bias,
                                              float* __restrict__ Y,
                                              const int* __restrict__ rmask)
{
    __shared__ __align__(128) char sm[2 * STGB];

    const int tid  = threadIdx.x;
    const int lane = tid & 31;
    const int w    = tid >> 5;
    const int m0   = (w >> 1) * 32;
    const int n0   = (w & 1) * 32;
    const int bm   = blockIdx.y * BM;
    const int bn   = blockIdx.x * BN;
    const uint32_t sbase = smem_u32(sm);

    float acc[2][4][4];
#pragma unroll
    for (int mt = 0; mt < 2; ++mt)
#pragma unroll
        for (int nt = 0; nt < 4; ++nt)
#pragma unroll
            for (int i = 0; i < 4; ++i) acc[mt][nt][i] = 0.f;

    {
        float4 av[4]; float bv[8];
        load_regs(X, W, bm, bn, 0, tid, av, bv);
        store_stage(sm, tid, av, bv);
    }
    __syncthreads();

    for (int t = 0; t < NT; ++t) {
        const int cur = t & 1;
        float4 av[4]; float bv[8];
        const bool pf = (t + 1 < NT);
        if (pf) load_regs(X, W, bm, bn, (t + 1) * BK, tid, av, bv);

        const uint32_t sA = sbase + cur * STGB;
        const uint32_t sB = sA + BHI;
#pragma unroll
        for (int ks = 0; ks < 2; ++ks) {
            uint32_t ah[2][4], al[2][4], bh[4][2], bl[4][2];
#pragma unroll
            for (int mt = 0; mt < 2; ++mt) {
                const int row = m0 + mt * 16 + (lane & 15);
                const int ch  = ks * 2 + (lane >> 4);
                const uint32_t ad = sA + sw_off(row, ch);
                LDMX4(ah[mt], ad);
                LDMX4(al[mt], ad + ALO);
            }
#pragma unroll
            for (int np = 0; np < 2; ++np) {
                const int nr = n0 + np * 16 + ((lane >> 4) << 3) + (lane & 7);
                const int ch = ks * 2 + ((lane >> 3) & 1);
                const uint32_t ad = sB + sw_off(nr, ch);
                uint32_t th[4], tl[4];
                LDMX4(th, ad);
                LDMX4(tl, ad + (BLO - BHI));
                bh[np * 2][0] = th[0]; bh[np * 2][1] = th[1];
                bh[np * 2 + 1][0] = th[2]; bh[np * 2 + 1][1] = th[3];
                bl[np * 2][0] = tl[0]; bl[np * 2][1] = tl[1];
                bl[np * 2 + 1][0] = tl[2]; bl[np * 2 + 1][1] = tl[3];
            }
#pragma unroll
            for (int mt = 0; mt < 2; ++mt)
#pragma unroll
                for (int nt = 0; nt < 4; ++nt) {
                    MMA_BF16(acc[mt][nt], ah[mt], bh[nt]);
                    MMA_BF16(acc[mt][nt], ah[mt], bl[nt]);
                    MMA_BF16(acc[mt][nt], al[mt], bh[nt]);
                }
        }
        if (pf) store_stage(sm + (cur ^ 1) * STGB, tid, av, bv);
        __syncthreads();
    }

#pragma unroll
    for (int nt = 0; nt < 4; ++nt) {
        const int gc = bn + n0 + nt * 8 + (lane & 3) * 2;
        const float b0 = bias[gc], b1 = bias[gc + 1];
#pragma unroll
        for (int mt = 0; mt < 2; ++mt) {
            const int gr = bm + m0 + mt * 16 + (lane >> 2);
            const float s0 = rmask ? (float)rmask[gr] : 1.f;
            const float s1 = rmask ? (float)rmask[gr + 8] : 1.f;
            float2 v0, v1;
            v0.x = (acc[mt][nt][0] + b0) * s0;
            v0.y = (acc[mt][nt][1] + b1) * s0;
            v1.x = (acc[mt][nt][2] + b0) * s1;
            v1.y = (acc[mt][nt][3] + b1) * s1;
            *(float2*)(Y + (size_t)gr * NN + gc)       = v0;
            *(float2*)(Y + (size_t)(gr + 8) * NN + gc) = v1;
        }
    }
}

__global__ __launch_bounds__(256, 2)
void mma_gemm_qkv(const float* q, const float* k, const float* v,
                  const float* Wq, const float* bq,
                  const float* Wk, const float* bk,
                  const float* Wv, const float* bv)
{
    const float* X; const float* W; const float* bias; float* Y;
    if (blockIdx.z == 0)      { X = q; W = Wq; bias = bq; Y = g_qw; }
    else if (blockIdx.z == 1) { X = k; W = Wk; bias = bk; Y = g_kw; }
    else                      { X = v; W = Wv; bias = bv; Y = g_vw; }
    mma_gemm_body(X, W, bias, Y, nullptr);
}

__global__ __launch_bounds__(256, 2)
void mma_gemm_out(const float* Wo, const float* bo, float* out,
                  const int* qmask)
{
    mma_gemm_body(g_at, Wo, bo, out, qmask);
}

// ===========================================================================
// Flash attention on tensor cores (FA2 style, split-bf16 3-pass).
// 128 threads = 4 warps; warp w owns q-rows [w*16, w*16+16) of a 64-row tile.
// STATIC smem = 48KB exactly: Qh Ql Kh Kl Vh Vl (64x64 bf16, swizzled rows).
// v_mask penalties read per-thread from global (L1-resident).
// Masking semantics identical to reference (additive -1e12 fp32).
// ===========================================================================
constexpr int FQH = 0,     FQL = 8192,  FKH = 16384, FKL = 24576;
constexpr int FVH = 32768, FVL = 40960;

__global__ __launch_bounds__(128, 3)
void flash_mma_kernel(const int* __restrict__ v_mask)
{
    __shared__ __align__(128) char fsm[49152];
    const uint32_t sb = smem_u32(fsm);
    const int tid  = threadIdx.x;
    const int lane = tid & 31;
    const int w    = tid >> 5;
    const int m0   = w * 16;
    const int bh   = blockIdx.y;
    const int b    = bh >> 4;
    const int h    = bh & 15;
    const int q0   = blockIdx.x * 64;
    const int hc   = h * 64;

    // ---- load Q tile -> Qh/Ql (swizzled) ----
    {
        const int r   = tid >> 1;
        const int f40 = (tid & 1) * 8;
        const float* src = g_qw + (size_t)(b * S + q0 + r) * NN + hc + f40 * 4;
#pragma unroll
        for (int f = 0; f < 8; ++f) {
            float4 vq = *(const float4*)(src + f * 4);
            const int f4 = f40 + f;
            const int off = fsw(r, f4 >> 1) + (f4 & 1) * 8;
            uint2 e;
            e.x = pk2(vq.x, vq.y); e.y = pk2(vq.z, vq.w);
            *(uint2*)(fsm + FQH + off) = e;
            e.x = pk2(bres(vq.x), bres(vq.y));
            e.y = pk2(bres(vq.z), bres(vq.w));
            *(uint2*)(fsm + FQL + off) = e;
        }
    }
    __syncthreads();

    // ---- Q fragments (held in registers for all kv tiles) ----
    uint32_t qh[4][4], ql[4][4];
#pragma unroll
    for (int ks = 0; ks < 4; ++ks) {
        const int row = m0 + (lane & 15);
        const int ch  = ks * 2 + (lane >> 4);
        const uint32_t ad = sb + FQH + fsw(row, ch);
        LDMX4(qh[ks], ad);
        LDMX4(ql[ks], ad + (FQL - FQH));
    }

    const float NEGINF = __int_as_float(0xff800000);
    float m_[2] = {NEGINF, NEGINF};
    float l_[2] = {0.f, 0.f};
    float o[8][4];
#pragma unroll
    for (int nt = 0; nt < 8; ++nt)
#pragma unroll
        for (int i = 0; i < 4; ++i) o[nt][i] = 0.f;

    const int diag = blockIdx.x;

    for (int t = 0; t < 16; ++t) {
        __syncthreads();   // previous tile's smem reads complete
        // ---- load K,V tiles (hi/lo) ----
        {
            const int r   = tid >> 1;
            const int f40 = (tid & 1) * 8;
            const size_t base = (size_t)(b * S + t * 64 + r) * NN + hc + f40 * 4;
            const float* ksrc = g_kw + base;
            const float* vsrc = g_vw + base;
#pragma unroll
            for (int f = 0; f < 8; ++f) {
                float4 kv = *(const float4*)(ksrc + f * 4);
                float4 vv = *(const float4*)(vsrc + f * 4);
                const int f4  = f40 + f;
                const int off = fsw(r, f4 >> 1) + (f4 & 1) * 8;
                uint2 e;
                e.x = pk2(kv.x, kv.y); e.y = pk2(kv.z, kv.w);
                *(uint2*)(fsm + FKH + off) = e;
                e.x = pk2(bres(kv.x), bres(kv.y));
                e.y = pk2(bres(kv.z), bres(kv.w));
                *(uint2*)(fsm + FKL + off) = e;
                e.x = pk2(vv.x, vv.y); e.y = pk2(vv.z, vv.w);
                *(uint2*)(fsm + FVH + off) = e;
                e.x = pk2(bres(vv.x), bres(vv.y));
                e.y = pk2(bres(vv.z), bres(vv.w));
                *(uint2*)(fsm + FVL + off) = e;
            }
        }
        __syncthreads();

        // ---- S = Q K^T (split-bf16, 3 passes) ----
        float sc[8][4];
#pragma unroll
        for (int nt = 0; nt < 8; ++nt)
#pragma unroll
            for (int i = 0; i < 4; ++i) sc[nt][i] = 0.f;
#pragma unroll
        for (int ks = 0; ks < 4; ++ks) {
            uint32_t kbh[8][2], kbl[8][2];
#pragma unroll
            for (int np = 0; np < 4; ++np) {
                const int nr = np * 16 + ((lane >> 4) << 3) + (lane & 7);
                const int ch = ks * 2 + ((lane >> 3) & 1);
                const uint32_t ad = sb + FKH + fsw(nr, ch);
                uint32_t th[4], tl[4];
                LDMX4(th, ad);
                LDMX4(tl, ad + (FKL - FKH));
                kbh[np * 2][0] = th[0]; kbh[np * 2][1] = th[1];
                kbh[np * 2 + 1][0] = th[2]; kbh[np * 2 + 1][1] = th[3];
                kbl[np * 2][0] = tl[0]; kbl[np * 2][1] = tl[1];
                kbl[np * 2 + 1][0] = tl[2]; kbl[np * 2 + 1][1] = tl[3];
            }
#pragma unroll
            for (int nt = 0; nt < 8; ++nt) {
                MMA_BF16(sc[nt], qh[ks], kbh[nt]);
                MMA_BF16(sc[nt], qh[ks], kbl[nt]);
                MMA_BF16(sc[nt], ql[ks], kbh[nt]);
            }
        }

        // ---- mask + online softmax (v_mask straight from global/L1) ----
        const int r0g = q0 + m0 + (lane >> 2);
        const int r1g = r0g + 8;
        const int vmb = b * S + t * 64;
        float tmax0 = NEGINF, tmax1 = NEGINF;
#pragma unroll
        for (int nt = 0; nt < 8; ++nt) {
            const int c0  = nt * 8 + (lane & 3) * 2;
            const int cg0 = t * 64 + c0;
            const float p0 = (1.0f - (float)__ldg(&v_mask[vmb + c0]))     * 1e12f;
            const float p1 = (1.0f - (float)__ldg(&v_mask[vmb + c0 + 1])) * 1e12f;
            float s0 = sc[nt][0] * 0.125f - p0; if (cg0     > r0g) s0 -= 1e12f;
            float s1 = sc[nt][1] * 0.125f - p1; if (cg0 + 1 > r0g) s1 -= 1e12f;
            float s2 = sc[nt][2] * 0.125f - p0; if (cg0     > r1g) s2 -= 1e12f;
            float s3 = sc[nt][3] * 0.125f - p1; if (cg0 + 1 > r1g) s3 -= 1e12f;
            sc[nt][0] = s0; sc[nt][1] = s1; sc[nt][2] = s2; sc[nt][3] = s3;
            tmax0 = fmaxf(tmax0, fmaxf(s0, s1));
            tmax1 = fmaxf(tmax1, fmaxf(s2, s3));
        }
        tmax0 = fmaxf(tmax0, __shfl_xor_sync(0xffffffffu, tmax0, 1));
        tmax0 = fmaxf(tmax0, __shfl_xor_sync(0xffffffffu, tmax0, 2));
        tmax1 = fmaxf(tmax1, __shfl_xor_sync(0xffffffffu, tmax1, 1));
        tmax1 = fmaxf(tmax1, __shfl_xor_sync(0xffffffffu, tmax1, 2));
        const float mn0 = fmaxf(m_[0], tmax0);
        const float mn1 = fmaxf(m_[1], tmax1);
        const float al0 = __expf(m_[0] - mn0);
        const float al1 = __expf(m_[1] - mn1);
        float rs0 = 0.f, rs1 = 0.f;
#pragma unroll
        for (int nt = 0; nt < 8; ++nt) {
            sc[nt][0] = __expf(sc[nt][0] - mn0); rs0 += sc[nt][0];
            sc[nt][1] = __expf(sc[nt][1] - mn0); rs0 += sc[nt][1];
            sc[nt][2] = __expf(sc[nt][2] - mn1); rs1 += sc[nt][2];
            sc[nt][3] = __expf(sc[nt][3] - mn1); rs1 += sc[nt][3];
        }
        rs0 += __shfl_xor_sync(0xffffffffu, rs0, 1);
        rs0 += __shfl_xor_sync(0xffffffffu, rs0, 2);
        rs1 += __shfl_xor_sync(0xffffffffu, rs1, 1);
        rs1 += __shfl_xor_sync(0xffffffffu, rs1, 2);
        l_[0] = l_[0] * al0 + rs0;
        l_[1] = l_[1] * al1 + rs1;
        m_[0] = mn0;
        m_[1] = mn1;
#pragma unroll
        for (int nt = 0; nt < 8; ++nt) {
            o[nt][0] *= al0; o[nt][1] *= al0;
            o[nt][2] *= al1; o[nt][3] *= al1;
        }

        // ---- O += P V (P repacked in registers; V via ldmatrix.trans) ----
#pragma unroll
        for (int kt = 0; kt < 4; ++kt) {
            uint32_t pah[4], pal[4];
            pah[0] = pk2(sc[2 * kt][0],     sc[2 * kt][1]);
            pah[1] = pk2(sc[2 * kt][2],     sc[2 * kt][3]);
            pah[2] = pk2(sc[2 * kt + 1][0], sc[2 * kt + 1][1]);
            pah[3] = pk2(sc[2 * kt + 1][2], sc[2 * kt + 1][3]);
            pal[0] = pk2(bres(sc[2 * kt][0]),     bres(sc[2 * kt][1]));
            pal[1] = pk2(bres(sc[2 * kt][2]),     bres(sc[2 * kt][3]));
            pal[2] = pk2(bres(sc[2 * kt + 1][0]), bres(sc[2 * kt + 1][1]));
            pal[3] = pk2(bres(sc[2 * kt + 1][2]), bres(sc[2 * kt + 1][3]));
#pragma unroll
            for (int np = 0; np < 4; ++np) {
                const int key = kt * 16 + (lane & 7) + ((lane >> 3) & 1) * 8;
                const int ch  = np * 2 + (lane >> 4);
                const uint32_t ad = sb + FVH + fsw(key, ch);
                uint32_t vh4[4], vl4[4];
                LDMX4T(vh4, ad);
                LDMX4T(vl4, ad + (FVL - FVH));
                uint32_t vb0h[2] = {vh4[0], vh4[1]}, vb1h[2] = {vh4[2], vh4[3]};
                uint32_t vb0l[2] = {vl4[0], vl4[1]}, vb1l[2] = {vl4[2], vl4[3]};
                MMA_BF16(o[np * 2],     pah, vb0h);
                MMA_BF16(o[np * 2],     pah, vb0l);
                MMA_BF16(o[np * 2],     pal, vb0h);
                MMA_BF16(o[np * 2 + 1], pah, vb1h);
                MMA_BF16(o[np * 2 + 1], pah, vb1l);
                MMA_BF16(o[np * 2 + 1], pal, vb1h);
            }
        }

        // Past diagonal: continue only while some row is still fully masked
        if (t >= diag) {
            int pred = (mn0 <= -1e11f) | (mn1 <= -1e11f);
            if (!__syncthreads_or(pred)) break;
        }
    }

    // ---- normalize + store ----
    const float inv0 = 1.0f / l_[0];
    const float inv1 = 1.0f / l_[1];
    const int gr0 = b * S + q0 + m0 + (lane >> 2);
#pragma unroll
    for (int nt = 0; nt < 8; ++nt) {
        const int col = hc + nt * 8 + (lane & 3) * 2;
        float2 v0, v1;
        v0.x = o[nt][0] * inv0; v0.y = o[nt][1] * inv0;
        v1.x = o[nt][2] * inv1; v1.y = o[nt][3] * inv1;
        *(float2*)&g_at[(size_t)gr0 * NN + col]       = v0;
        *(float2*)&g_at[(size_t)(gr0 + 8) * NN + col] = v1;
    }
}

// ---------------------------------------------------------------------------
extern "C" void kernel_launch(void* const* d_in, const int* in_sizes, int n_in,
                              void* d_out, int out_size)
{
    (void)in_sizes; (void)n_in; (void)out_size;
    const float* q     = (const float*)d_in[0];
    const float* k     = (const float*)d_in[1];
    const float* v     = (const float*)d_in[2];
    const int*   vmask = (const int*)  d_in[3];
    const int*   qmask = (const int*)  d_in[4];
    const float* Wq = (const float*)d_in[6];
    const float* bq = (const float*)d_in[7];
    const float* Wk = (const float*)d_in[8];
    const float* bk = (const float*)d_in[9];
    const float* Wv = (const float*)d_in[10];
    const float* bv = (const float*)d_in[11];
    const float* Wo = (const float*)d_in[12];
    const float* bo = (const float*)d_in[13];
    float* out = (float*)d_out;

    mma_gemm_qkv<<<dim3(NN / BN, M / BM, 3), 256>>>(q, k, v,
                                                    Wq, bq, Wk, bk, Wv, bv);
    flash_mma_kernel<<<dim3(S / 64, B * H), 128>>>(vmask);
    mma_gemm_out<<<dim3(NN / BN, M / BM), 256>>>(Wo, bo, out, qmask);
}

// round 10
// speedup vs baseline: 2.7010x; 1.1548x over previous
#include <cuda_runtime.h>
#include <cuda_bf16.h>
#include <math.h>
#include <stdint.h>

// Problem constants
constexpr int B  = 4;
constexpr int S  = 1024;
constexpr int H  = 16;
constexpr int M  = B * S;          // 4096
constexpr int NN = H * 64;         // 1024
constexpr int KK = 1024;

// ===========================================================================
// Global scratch (device globals: allocation-free). bf16 hi/lo dataflow.
// ===========================================================================
__device__ __nv_bfloat16 g_xh[3][(size_t)M * KK];   // converted inputs q,k,v
__device__ __nv_bfloat16 g_xl[3][(size_t)M * KK];
__device__ __nv_bfloat16 g_wth[4][(size_t)NN * KK]; // transposed weights [n][k]
__device__ __nv_bfloat16 g_wtl[4][(size_t)NN * KK];
__device__ __nv_bfloat16 g_oh[3][(size_t)M * NN];   // qw,kw,vw (proj outputs)
__device__ __nv_bfloat16 g_ol[3][(size_t)M * NN];
__device__ __nv_bfloat16 g_ath[(size_t)M * NN];     // attention output
__device__ __nv_bfloat16 g_atl[(size_t)M * NN];

// ===========================================================================
// Helpers
// ===========================================================================
__device__ __forceinline__ uint32_t smem_u32(const void* p) {
    uint32_t a;
    asm("{ .reg .u64 t; cvta.to.shared.u64 t, %1; cvt.u32.u64 %0, t; }"
        : "=r"(a) : "l"(p));
    return a;
}
__device__ __forceinline__ uint64_t gaddr(const void* p) {
    uint64_t r;
    asm("cvta.to.global.u64 %0, %1;" : "=l"(r) : "l"(p));
    return r;
}
__device__ __forceinline__ uint32_t pk2(float a, float b) {
    __nv_bfloat162 t;
    t.x = __float2bfloat16(a);
    t.y = __float2bfloat16(b);
    return *(uint32_t*)&t;
}
__device__ __forceinline__ float bres(float x) {   // residual after bf16 hi
    __nv_bfloat16 h = __float2bfloat16(x);
    return x - __bfloat162float(h);
}

// 64B-row swizzle (GEMM tiles: 32 bf16 per row), chunk 0..3
__device__ __forceinline__ int sw_off(int row, int chunk) {
    return row * 64 + ((chunk ^ ((row >> 1) & 3) ^ ((row >> 3) & 3)) << 4);
}
// 128B-row swizzle (flash tiles: 64 bf16 per row), chunk 0..7
__device__ __forceinline__ int fsw(int row, int chunk) {
    return row * 128 + ((chunk ^ (row & 7)) << 4);
}

#define LDMX4(r, addr) \
    asm volatile("ldmatrix.sync.aligned.m8n8.x4.shared.b16 {%0,%1,%2,%3}, [%4];" \
        : "=r"((r)[0]), "=r"((r)[1]), "=r"((r)[2]), "=r"((r)[3]) : "r"(addr))
#define LDMX4T(r, addr) \
    asm volatile("ldmatrix.sync.aligned.m8n8.x4.trans.shared.b16 {%0,%1,%2,%3}, [%4];" \
        : "=r"((r)[0]), "=r"((r)[1]), "=r"((r)[2]), "=r"((r)[3]) : "r"(addr))
#define MMA_BF16(d, a, bb) \
    asm volatile("mma.sync.aligned.m16n8k16.row.col.f32.bf16.bf16.f32 " \
        "{%0,%1,%2,%3}, {%4,%5,%6,%7}, {%8,%9}, {%0,%1,%2,%3};" \
        : "+f"((d)[0]), "+f"((d)[1]), "+f"((d)[2]), "+f"((d)[3]) \
        : "r"((a)[0]), "r"((a)[1]), "r"((a)[2]), "r"((a)[3]), \
          "r"((bb)[0]), "r"((bb)[1]))
#define CP16(dst, src) \
    asm volatile("cp.async.cg.shared.global [%0], [%1], 16;" \
        :: "r"((uint32_t)(dst)), "l"((uint64_t)(src)))
#define CP_COMMIT() asm volatile("cp.async.commit_group;" ::: "memory")
#define CP_WAIT0()  asm volatile("cp.async.wait_group 0;" ::: "memory")
#define CP_WAIT1()  asm volatile("cp.async.wait_group 1;" ::: "memory")

// ===========================================================================
// Conversion kernels (run once per call, ~35us total)
// ===========================================================================
__global__ void conv_in(const float* __restrict__ q,
                        const float* __restrict__ k,
                        const float* __restrict__ v)
{
    const int z = blockIdx.z;
    const float* src = (z == 0) ? q : (z == 1) ? k : v;
    uint2* dh = (uint2*)g_xh[z];
    uint2* dl = (uint2*)g_xl[z];
    const int n4 = M * KK / 4;
    for (int i = blockIdx.x * blockDim.x + threadIdx.x; i < n4;
         i += gridDim.x * blockDim.x) {
        float4 x = ((const float4*)src)[i];
        uint2 hi, lo;
        hi.x = pk2(x.x, x.y);             hi.y = pk2(x.z, x.w);
        lo.x = pk2(bres(x.x), bres(x.y)); lo.y = pk2(bres(x.z), bres(x.w));
        dh[i] = hi;
        dl[i] = lo;
    }
}

__global__ void conv_w(const float* __restrict__ Wq, const float* __restrict__ Wk,
                       const float* __restrict__ Wv, const float* __restrict__ Wo)
{
    __shared__ float t[32][33];
    const int z = blockIdx.z;
    const float* W = (z == 0) ? Wq : (z == 1) ? Wk : (z == 2) ? Wv : Wo;
    __nv_bfloat16* th = g_wth[z];
    __nv_bfloat16* tl = g_wtl[z];
    const int nb = blockIdx.x * 32, kb = blockIdx.y * 32;
    const int tx = threadIdx.x, ty = threadIdx.y;
#pragma unroll
    for (int j = 0; j < 4; ++j)
        t[ty + 8 * j][tx] = W[(size_t)(kb + ty + 8 * j) * NN + nb + tx];
    __syncthreads();
#pragma unroll
    for (int j = 0; j < 4; ++j) {
        const float val = t[tx][ty + 8 * j];
        const size_t o = (size_t)(nb + ty + 8 * j) * KK + kb + tx;
        __nv_bfloat16 h = __float2bfloat16(val);
        th[o] = h;
        tl[o] = __float2bfloat16(val - __bfloat162float(h));
    }
}

// ===========================================================================
// cp.async bf16 split GEMM core: 128(M) x 64(N), BK=32, 256 threads,
// 8 warps (4m x 2n, warp 32x32). 2 stages x 24KB = 48KB static smem.
// A, B already bf16 hi/lo in global (B pre-transposed [n][k]).
// ===========================================================================
constexpr int BM = 128, BN = 64, BK = 32;
constexpr int STGB = 24576;
constexpr int AHI = 0, ALO = 8192, BHI = 16384, BLO = 20480;
constexpr int NT = KK / BK;

__device__ __forceinline__ void gemm_issue(uint64_t Ah, uint64_t Al,
                                           uint64_t Bh, uint64_t Bl,
                                           int k0, int tid, uint32_t stg)
{
    const int r = tid >> 2, c = tid & 3;
    const uint64_t ko = (uint64_t)(k0 + c * 8) * 2;
    const uint64_t so  = (uint64_t)r * (KK * 2) + ko;
    const uint64_t so2 = (uint64_t)(r + 64) * (KK * 2) + ko;
    const int sw  = sw_off(r, c);
    const int sw2 = sw_off(r + 64, c);
    CP16(stg + AHI + sw,  Ah + so);
    CP16(stg + ALO + sw,  Al + so);
    CP16(stg + AHI + sw2, Ah + so2);
    CP16(stg + ALO + sw2, Al + so2);
    CP16(stg + BHI + sw,  Bh + so);
    CP16(stg + BLO + sw,  Bl + so);
}

__device__ __forceinline__ void gemm_core(uint64_t Ah, uint64_t Al,
                                          uint64_t Bh, uint64_t Bl,
                                          int m0, int n0, int lane,
                                          float acc[2][4][4])
{
    __shared__ __align__(128) char sm[2 * STGB];
    const uint32_t sbase = smem_u32(sm);
    const int tid = threadIdx.x;

#pragma unroll
    for (int mt = 0; mt < 2; ++mt)
#pragma unroll
        for (int nt = 0; nt < 4; ++nt)
#pragma unroll
            for (int i = 0; i < 4; ++i) acc[mt][nt][i] = 0.f;

    gemm_issue(Ah, Al, Bh, Bl, 0, tid, sbase);
    CP_COMMIT();

    for (int t = 0; t < NT; ++t) {
        if (t + 1 < NT) {
            gemm_issue(Ah, Al, Bh, Bl, (t + 1) * BK, tid,
                       sbase + ((t + 1) & 1) * STGB);
            CP_COMMIT();
            CP_WAIT1();
        } else {
            CP_WAIT0();
        }
        __syncthreads();

        const uint32_t sA = sbase + (t & 1) * STGB;
        const uint32_t sB = sA + BHI;
#pragma unroll
        for (int ks = 0; ks < 2; ++ks) {
            uint32_t ah[2][4], al[2][4], bh2[4][2], bl2[4][2];
#pragma unroll
            for (int mt = 0; mt < 2; ++mt) {
                const int row = m0 + mt * 16 + (lane & 15);
                const int ch  = ks * 2 + (lane >> 4);
                const uint32_t ad = sA + sw_off(row, ch);
                LDMX4(ah[mt], ad);
                LDMX4(al[mt], ad + ALO);
            }
#pragma unroll
            for (int np = 0; np < 2; ++np) {
                const int nr = n0 + np * 16 + ((lane >> 4) << 3) + (lane & 7);
                const int ch = ks * 2 + ((lane >> 3) & 1);
                const uint32_t ad = sB + sw_off(nr, ch);
                uint32_t th[4], tl[4];
                LDMX4(th, ad);
                LDMX4(tl, ad + (BLO - BHI));
                bh2[np * 2][0] = th[0]; bh2[np * 2][1] = th[1];
                bh2[np * 2 + 1][0] = th[2]; bh2[np * 2 + 1][1] = th[3];
                bl2[np * 2][0] = tl[0]; bl2[np * 2][1] = tl[1];
                bl2[np * 2 + 1][0] = tl[2]; bl2[np * 2 + 1][1] = tl[3];
            }
#pragma unroll
            for (int mt = 0; mt < 2; ++mt)
#pragma unroll
                for (int nt = 0; nt < 4; ++nt) {
                    MMA_BF16(acc[mt][nt], ah[mt], bh2[nt]);
                    MMA_BF16(acc[mt][nt], ah[mt], bl2[nt]);
                    MMA_BF16(acc[mt][nt], al[mt], bh2[nt]);
                }
        }
        __syncthreads();
    }
}

// QKV projection: writes bf16 hi/lo outputs for flash
__global__ __launch_bounds__(256, 2)
void qkv_v2(const float* __restrict__ bq, const float* __restrict__ bk,
            const float* __restrict__ bv)
{
    const int z = blockIdx.z;
    const float* bias = (z == 0) ? bq : (z == 1) ? bk : bv;
    const int tid = threadIdx.x, lane = tid & 31, w = tid >> 5;
    const int m0 = (w >> 1) * 32, n0 = (w & 1) * 32;
    const int bm = blockIdx.y * BM, bn = blockIdx.x * BN;

    const uint64_t Ah = gaddr(g_xh[z])  + (uint64_t)bm * KK * 2;
    const uint64_t Al = gaddr(g_xl[z])  + (uint64_t)bm * KK * 2;
    const uint64_t Bh = gaddr(g_wth[z]) + (uint64_t)bn * KK * 2;
    const uint64_t Bl = gaddr(g_wtl[z]) + (uint64_t)bn * KK * 2;

    float acc[2][4][4];
    gemm_core(Ah, Al, Bh, Bl, m0, n0, lane, acc);

    __nv_bfloat16* Yh = g_oh[z];
    __nv_bfloat16* Yl = g_ol[z];
#pragma unroll
    for (int nt = 0; nt < 4; ++nt) {
        const int gc = bn + n0 + nt * 8 + (lane & 3) * 2;
        const float b0 = bias[gc], b1 = bias[gc + 1];
#pragma unroll
        for (int mt = 0; mt < 2; ++mt) {
            const int gr = bm + m0 + mt * 16 + (lane >> 2);
            const float y0 = acc[mt][nt][0] + b0;
            const float y1 = acc[mt][nt][1] + b1;
            const float y2 = acc[mt][nt][2] + b0;
            const float y3 = acc[mt][nt][3] + b1;
            *(uint32_t*)&Yh[(size_t)gr * NN + gc]       = pk2(y0, y1);
            *(uint32_t*)&Yl[(size_t)gr * NN + gc]       = pk2(bres(y0), bres(y1));
            *(uint32_t*)&Yh[(size_t)(gr + 8) * NN + gc] = pk2(y2, y3);
            *(uint32_t*)&Yl[(size_t)(gr + 8) * NN + gc] = pk2(bres(y2), bres(y3));
        }
    }
}

// Output projection: A = attention output (bf16 hi/lo), fp32 out, q_mask
__global__ __launch_bounds__(256, 2)
void out_v2(const float* __restrict__ bo, float* __restrict__ out,
            const int* __restrict__ qmask)
{
    const int tid = threadIdx.x, lane = tid & 31, w = tid >> 5;
    const int m0 = (w >> 1) * 32, n0 = (w & 1) * 32;
    const int bm = blockIdx.y * BM, bn = blockIdx.x * BN;

    const uint64_t Ah = gaddr(g_ath)    + (uint64_t)bm * KK * 2;
    const uint64_t Al = gaddr(g_atl)    + (uint64_t)bm * KK * 2;
    const uint64_t Bh = gaddr(g_wth[3]) + (uint64_t)bn * KK * 2;
    const uint64_t Bl = gaddr(g_wtl[3]) + (uint64_t)bn * KK * 2;

    float acc[2][4][4];
    gemm_core(Ah, Al, Bh, Bl, m0, n0, lane, acc);

#pragma unroll
    for (int nt = 0; nt < 4; ++nt) {
        const int gc = bn + n0 + nt * 8 + (lane & 3) * 2;
        const float b0 = bo[gc], b1 = bo[gc + 1];
#pragma unroll
        for (int mt = 0; mt < 2; ++mt) {
            const int gr = bm + m0 + mt * 16 + (lane >> 2);
            const float s0 = (float)qmask[gr];
            const float s1 = (float)qmask[gr + 8];
            float2 v0, v1;
            v0.x = (acc[mt][nt][0] + b0) * s0;
            v0.y = (acc[mt][nt][1] + b1) * s0;
            v1.x = (acc[mt][nt][2] + b0) * s1;
            v1.y = (acc[mt][nt][3] + b1) * s1;
            *(float2*)(out + (size_t)gr * NN + gc)       = v0;
            *(float2*)(out + (size_t)(gr + 8) * NN + gc) = v1;
        }
    }
}

// ===========================================================================
// Flash attention v2: 128 q-rows/CTA, 8 warps (warp w -> rows w*16..w*16+15),
// 256 threads, grid (8, 64). Static 48KB: QB 16KB (two-phase hi->lo),
// K hi/lo 16KB, V hi/lo 16KB. All operands pre-converted bf16, cp.async in.
// Masking semantics identical to reference (additive -1e12 fp32 + quirk).
// ===========================================================================
constexpr int FQB = 0, FKH2 = 16384, FKL2 = 24576, FVH2 = 32768, FVL2 = 40960;

__global__ __launch_bounds__(256, 2)
void flash_v2(const int* __restrict__ v_mask)
{
    __shared__ __align__(128) char fsm[49152];
    const uint32_t sb = smem_u32(fsm);
    const int tid  = threadIdx.x;
    const int lane = tid & 31;
    const int w    = tid >> 5;         // 0..7
    const int m0   = w * 16;           // 0..112
    const int bh   = blockIdx.y;
    const int b    = bh >> 4;
    const int h    = bh & 15;
    const int q0   = blockIdx.x * 128;
    const int hc   = h * 64;

    const uint64_t Qh = gaddr(g_oh[0]);
    const uint64_t Ql = gaddr(g_ol[0]);
    const uint64_t Kh = gaddr(g_oh[1]);
    const uint64_t Kl = gaddr(g_ol[1]);
    const uint64_t Vh = gaddr(g_oh[2]);
    const uint64_t Vl = gaddr(g_ol[2]);

    // ---- Q phase 1: hi into QB, read frags ----
    uint32_t qh[4][4], ql[4][4];
    {
#pragma unroll
        for (int i = 0; i < 4; ++i) {
            const int id = tid + i * 256;
            const int r = id >> 3, c = id & 7;
            CP16(sb + FQB + fsw(r, c),
                 Qh + ((uint64_t)(b * S + q0 + r) * NN + hc + c * 8) * 2);
        }
        CP_COMMIT(); CP_WAIT0();
    }
    __syncthreads();
#pragma unroll
    for (int ks = 0; ks < 4; ++ks) {
        const int row = m0 + (lane & 15);
        const int ch  = ks * 2 + (lane >> 4);
        LDMX4(qh[ks], sb + FQB + fsw(row, ch));
    }
    __syncthreads();
    // ---- Q phase 2: lo into QB (reuse), read frags ----
    {
#pragma unroll
        for (int i = 0; i < 4; ++i) {
            const int id = tid + i * 256;
            const int r = id >> 3, c = id & 7;
            CP16(sb + FQB + fsw(r, c),
                 Ql + ((uint64_t)(b * S + q0 + r) * NN + hc + c * 8) * 2);
        }
        CP_COMMIT(); CP_WAIT0();
    }
    __syncthreads();
#pragma unroll
    for (int ks = 0; ks < 4; ++ks) {
        const int row = m0 + (lane & 15);
        const int ch  = ks * 2 + (lane >> 4);
        LDMX4(ql[ks], sb + FQB + fsw(row, ch));
    }

    const float NEGINF = __int_as_float(0xff800000);
    float m_[2] = {NEGINF, NEGINF};
    float l_[2] = {0.f, 0.f};
    float o[8][4];
#pragma unroll
    for (int nt = 0; nt < 8; ++nt)
#pragma unroll
        for (int i = 0; i < 4; ++i) o[nt][i] = 0.f;

    const int diag2 = 2 * blockIdx.x + 1;   // last causal-needed tile

    for (int t = 0; t < 16; ++t) {
        __syncthreads();   // prior tile's smem reads complete
        // ---- cp.async K,V hi/lo tiles ----
        {
#pragma unroll
            for (int i = 0; i < 2; ++i) {
                const int id = tid + i * 256;
                const int r = id >> 3, c = id & 7;
                const uint64_t off =
                    ((uint64_t)(b * S + t * 64 + r) * NN + hc + c * 8) * 2;
                const int sw = fsw(r, c);
                CP16(sb + FKH2 + sw, Kh + off);
                CP16(sb + FKL2 + sw, Kl + off);
                CP16(sb + FVH2 + sw, Vh + off);
                CP16(sb + FVL2 + sw, Vl + off);
            }
            CP_COMMIT(); CP_WAIT0();
        }
        __syncthreads();

        // ---- S = Q K^T (split-bf16, 3 passes) ----
        float sc[8][4];
#pragma unroll
        for (int nt = 0; nt < 8; ++nt)
#pragma unroll
            for (int i = 0; i < 4; ++i) sc[nt][i] = 0.f;
#pragma unroll
        for (int ks = 0; ks < 4; ++ks) {
            uint32_t kbh[8][2], kbl[8][2];
#pragma unroll
            for (int np = 0; np < 4; ++np) {
                const int nr = np * 16 + ((lane >> 4) << 3) + (lane & 7);
                const int ch = ks * 2 + ((lane >> 3) & 1);
                const uint32_t ad = sb + FKH2 + fsw(nr, ch);
                uint32_t th[4], tl[4];
                LDMX4(th, ad);
                LDMX4(tl, ad + (FKL2 - FKH2));
                kbh[np * 2][0] = th[0]; kbh[np * 2][1] = th[1];
                kbh[np * 2 + 1][0] = th[2]; kbh[np * 2 + 1][1] = th[3];
                kbl[np * 2][0] = tl[0]; kbl[np * 2][1] = tl[1];
                kbl[np * 2 + 1][0] = tl[2]; kbl[np * 2 + 1][1] = tl[3];
            }
#pragma unroll
            for (int nt = 0; nt < 8; ++nt) {
                MMA_BF16(sc[nt], qh[ks], kbh[nt]);
                MMA_BF16(sc[nt], qh[ks], kbl[nt]);
                MMA_BF16(sc[nt], ql[ks], kbh[nt]);
            }
        }

        // ---- mask + online softmax (v_mask from global/L1) ----
        const int r0g = q0 + m0 + (lane >> 2);
        const int r1g = r0g + 8;
        const int vmb = b * S + t * 64;
        float tmax0 = NEGINF, tmax1 = NEGINF;
#pragma unroll
        for (int nt = 0; nt < 8; ++nt) {
            const int c0  = nt * 8 + (lane & 3) * 2;
            const int cg0 = t * 64 + c0;
            const float p0 = (1.0f - (float)__ldg(&v_mask[vmb + c0]))     * 1e12f;
            const float p1 = (1.0f - (float)__ldg(&v_mask[vmb + c0 + 1])) * 1e12f;
            float s0 = sc[nt][0] * 0.125f - p0; if (cg0     > r0g) s0 -= 1e12f;
            float s1 = sc[nt][1] * 0.125f - p1; if (cg0 + 1 > r0g) s1 -= 1e12f;
            float s2 = sc[nt][2] * 0.125f - p0; if (cg0     > r1g) s2 -= 1e12f;
            float s3 = sc[nt][3] * 0.125f - p1; if (cg0 + 1 > r1g) s3 -= 1e12f;
            sc[nt][0] = s0; sc[nt][1] = s1; sc[nt][2] = s2; sc[nt][3] = s3;
            tmax0 = fmaxf(tmax0, fmaxf(s0, s1));
            tmax1 = fmaxf(tmax1, fmaxf(s2, s3));
        }
        tmax0 = fmaxf(tmax0, __shfl_xor_sync(0xffffffffu, tmax0, 1));
        tmax0 = fmaxf(tmax0, __shfl_xor_sync(0xffffffffu, tmax0, 2));
        tmax1 = fmaxf(tmax1, __shfl_xor_sync(0xffffffffu, tmax1, 1));
        tmax1 = fmaxf(tmax1, __shfl_xor_sync(0xffffffffu, tmax1, 2));
        const float mn0 = fmaxf(m_[0], tmax0);
        const float mn1 = fmaxf(m_[1], tmax1);
        const float al0 = __expf(m_[0] - mn0);
        const float al1 = __expf(m_[1] - mn1);
        float rs0 = 0.f, rs1 = 0.f;
#pragma unroll
        for (int nt = 0; nt < 8; ++nt) {
            sc[nt][0] = __expf(sc[nt][0] - mn0); rs0 += sc[nt][0];
            sc[nt][1] = __expf(sc[nt][1] - mn0); rs0 += sc[nt][1];
            sc[nt][2] = __expf(sc[nt][2] - mn1); rs1 += sc[nt][2];
            sc[nt][3] = __expf(sc[nt][3] - mn1); rs1 += sc[nt][3];
        }
        rs0 += __shfl_xor_sync(0xffffffffu, rs0, 1);
        rs0 += __shfl_xor_sync(0xffffffffu, rs0, 2);
        rs1 += __shfl_xor_sync(0xffffffffu, rs1, 1);
        rs1 += __shfl_xor_sync(0xffffffffu, rs1, 2);
        l_[0] = l_[0] * al0 + rs0;
        l_[1] = l_[1] * al1 + rs1;
        m_[0] = mn0;
        m_[1] = mn1;
#pragma unroll
        for (int nt = 0; nt < 8; ++nt) {
            o[nt][0] *= al0; o[nt][1] *= al0;
            o[nt][2] *= al1; o[nt][3] *= al1;
        }

        // ---- O += P V (P repacked in registers; V via ldmatrix.trans) ----
#pragma unroll
        for (int kt = 0; kt < 4; ++kt) {
            uint32_t pah[4], pal[4];
            pah[0] = pk2(sc[2 * kt][0],     sc[2 * kt][1]);
            pah[1] = pk2(sc[2 * kt][2],     sc[2 * kt][3]);
            pah[2] = pk2(sc[2 * kt + 1][0], sc[2 * kt + 1][1]);
            pah[3] = pk2(sc[2 * kt + 1][2], sc[2 * kt + 1][3]);
            pal[0] = pk2(bres(sc[2 * kt][0]),     bres(sc[2 * kt][1]));
            pal[1] = pk2(bres(sc[2 * kt][2]),     bres(sc[2 * kt][3]));
            pal[2] = pk2(bres(sc[2 * kt + 1][0]), bres(sc[2 * kt + 1][1]));
            pal[3] = pk2(bres(sc[2 * kt + 1][2]), bres(sc[2 * kt + 1][3]));
#pragma unroll
            for (int np = 0; np < 4; ++np) {
                const int key = kt * 16 + (lane & 7) + ((lane >> 3) & 1) * 8;
                const int ch  = np * 2 + (lane >> 4);
                const uint32_t ad = sb + FVH2 + fsw(key, ch);
                uint32_t vh4[4], vl4[4];
                LDMX4T(vh4, ad);
                LDMX4T(vl4, ad + (FVL2 - FVH2));
                uint32_t vb0h[2] = {vh4[0], vh4[1]}, vb1h[2] = {vh4[2], vh4[3]};
                uint32_t vb0l[2] = {vl4[0], vl4[1]}, vb1l[2] = {vl4[2], vl4[3]};
                MMA_BF16(o[np * 2],     pah, vb0h);
                MMA_BF16(o[np * 2],     pah, vb0l);
                MMA_BF16(o[np * 2],     pal, vb0h);
                MMA_BF16(o[np * 2 + 1], pah, vb1h);
                MMA_BF16(o[np * 2 + 1], pah, vb1l);
                MMA_BF16(o[np * 2 + 1], pal, vb1h);
            }
        }

        // Past diagonal: continue only while some row is still fully masked
        if (t >= diag2) {
            int pred = (mn0 <= -1e11f) | (mn1 <= -1e11f);
            if (!__syncthreads_or(pred)) break;
        }
    }

    // ---- normalize + store as bf16 hi/lo for the output projection ----
    const float inv0 = 1.0f / l_[0];
    const float inv1 = 1.0f / l_[1];
    const int gr0 = b * S + q0 + m0 + (lane >> 2);
#pragma unroll
    for (int nt = 0; nt < 8; ++nt) {
        const int col = hc + nt * 8 + (lane & 3) * 2;
        const float a0 = o[nt][0] * inv0, a1 = o[nt][1] * inv0;
        const float a2 = o[nt][2] * inv1, a3 = o[nt][3] * inv1;
        *(uint32_t*)&g_ath[(size_t)gr0 * NN + col]       = pk2(a0, a1);
        *(uint32_t*)&g_atl[(size_t)gr0 * NN + col]       = pk2(bres(a0), bres(a1));
        *(uint32_t*)&g_ath[(size_t)(gr0 + 8) * NN + col] = pk2(a2, a3);
        *(uint32_t*)&g_atl[(size_t)(gr0 + 8) * NN + col] = pk2(bres(a2), bres(a3));
    }
}

// ---------------------------------------------------------------------------
extern "C" void kernel_launch(void* const* d_in, const int* in_sizes, int n_in,
                              void* d_out, int out_size)
{
    (void)in_sizes; (void)n_in; (void)out_size;
    const float* q     = (const float*)d_in[0];
    const float* k     = (const float*)d_in[1];
    const float* v     = (const float*)d_in[2];
    const int*   vmask = (const int*)  d_in[3];
    const int*   qmask = (const int*)  d_in[4];
    const float* Wq = (const float*)d_in[6];
    const float* bq = (const float*)d_in[7];
    const float* Wk = (const float*)d_in[8];
    const float* bk = (const float*)d_in[9];
    const float* Wv = (const float*)d_in[10];
    const float* bv = (const float*)d_in[11];
    const float* Wo = (const float*)d_in[12];
    const float* bo = (const float*)d_in[13];
    float* out = (float*)d_out;

    conv_in<<<dim3(1024, 1, 3), 256>>>(q, k, v);
    conv_w<<<dim3(32, 32, 4), dim3(32, 8)>>>(Wq, Wk, Wv, Wo);
    qkv_v2<<<dim3(NN / BN, M / BM, 3), 256>>>(bq, bk, bv);
    flash_v2<<<dim3(S / 128, B * H), 256>>>(vmask);
    out_v2<<<dim3(NN / BN, M / BM), 256>>>(bo, out, qmask);
}

// round 12
// speedup vs baseline: 2.7691x; 1.0252x over previous
#include <cuda_runtime.h>
#include <cuda_bf16.h>
#include <math.h>
#include <stdint.h>

// Problem constants
constexpr int B  = 4;
constexpr int S  = 1024;
constexpr int H  = 16;
constexpr int M  = B * S;          // 4096
constexpr int NN = H * 64;         // 1024
constexpr int KK = 1024;

// ===========================================================================
// Global scratch (device globals: allocation-free). bf16 hi/lo dataflow.
// ===========================================================================
__device__ __nv_bfloat16 g_xh[3][(size_t)M * KK];   // converted inputs q,k,v
__device__ __nv_bfloat16 g_xl[3][(size_t)M * KK];
__device__ __nv_bfloat16 g_wth[4][(size_t)NN * KK]; // transposed weights [n][k]
__device__ __nv_bfloat16 g_wtl[4][(size_t)NN * KK];
__device__ __nv_bfloat16 g_oh[3][(size_t)M * NN];   // qw,kw,vw (proj outputs)
__device__ __nv_bfloat16 g_ol[3][(size_t)M * NN];
__device__ __nv_bfloat16 g_ath[(size_t)M * NN];     // attention output
__device__ __nv_bfloat16 g_atl[(size_t)M * NN];

// ===========================================================================
// Helpers
// ===========================================================================
__device__ __forceinline__ uint32_t smem_u32(const void* p) {
    uint32_t a;
    asm("{ .reg .u64 t; cvta.to.shared.u64 t, %1; cvt.u32.u64 %0, t; }"
        : "=r"(a) : "l"(p));
    return a;
}
__device__ __forceinline__ uint64_t gaddr(const void* p) {
    uint64_t r;
    asm("cvta.to.global.u64 %0, %1;" : "=l"(r) : "l"(p));
    return r;
}
__device__ __forceinline__ uint32_t pk2(float a, float b) {
    __nv_bfloat162 t;
    t.x = __float2bfloat16(a);
    t.y = __float2bfloat16(b);
    return *(uint32_t*)&t;
}
__device__ __forceinline__ float bres(float x) {   // residual after bf16 hi
    __nv_bfloat16 h = __float2bfloat16(x);
    return x - __bfloat162float(h);
}

// 64B-row swizzle (GEMM tiles: 32 bf16 per row), chunk 0..3
__device__ __forceinline__ int sw_off(int row, int chunk) {
    return row * 64 + ((chunk ^ ((row >> 1) & 3) ^ ((row >> 3) & 3)) << 4);
}
// 128B-row swizzle (flash tiles: 64 bf16 per row), chunk 0..7
__device__ __forceinline__ int fsw(int row, int chunk) {
    return row * 128 + ((chunk ^ (row & 7)) << 4);
}

#define LDMX4(r, addr) \
    asm volatile("ldmatrix.sync.aligned.m8n8.x4.shared.b16 {%0,%1,%2,%3}, [%4];" \
        : "=r"((r)[0]), "=r"((r)[1]), "=r"((r)[2]), "=r"((r)[3]) : "r"(addr))
#define LDMX4T(r, addr) \
    asm volatile("ldmatrix.sync.aligned.m8n8.x4.trans.shared.b16 {%0,%1,%2,%3}, [%4];" \
        : "=r"((r)[0]), "=r"((r)[1]), "=r"((r)[2]), "=r"((r)[3]) : "r"(addr))
#define MMA_BF16(d, a, bb) \
    asm volatile("mma.sync.aligned.m16n8k16.row.col.f32.bf16.bf16.f32 " \
        "{%0,%1,%2,%3}, {%4,%5,%6,%7}, {%8,%9}, {%0,%1,%2,%3};" \
        : "+f"((d)[0]), "+f"((d)[1]), "+f"((d)[2]), "+f"((d)[3]) \
        : "r"((a)[0]), "r"((a)[1]), "r"((a)[2]), "r"((a)[3]), \
          "r"((bb)[0]), "r"((bb)[1]))
#define CP16(dst, src) \
    asm volatile("cp.async.cg.shared.global [%0], [%1], 16;" \
        :: "r"((uint32_t)(dst)), "l"((uint64_t)(src)))
#define CP_COMMIT() asm volatile("cp.async.commit_group;" ::: "memory")
#define CP_WAIT0()  asm volatile("cp.async.wait_group 0;" ::: "memory")
#define CP_WAIT1()  asm volatile("cp.async.wait_group 1;" ::: "memory")
#define CP_WAIT2()  asm volatile("cp.async.wait_group 2;" ::: "memory")

// ===========================================================================
// Conversion kernels (run once per call, ~25us total)
// ===========================================================================
__global__ void conv_in(const float* __restrict__ q,
                        const float* __restrict__ k,
                        const float* __restrict__ v)
{
    const int z = blockIdx.z;
    const float* src = (z == 0) ? q : (z == 1) ? k : v;
    uint2* dh = (uint2*)g_xh[z];
    uint2* dl = (uint2*)g_xl[z];
    const int n4 = M * KK / 4;
    for (int i = blockIdx.x * blockDim.x + threadIdx.x; i < n4;
         i += gridDim.x * blockDim.x) {
        float4 x = ((const float4*)src)[i];
        uint2 hi, lo;
        hi.x = pk2(x.x, x.y);             hi.y = pk2(x.z, x.w);
        lo.x = pk2(bres(x.x), bres(x.y)); lo.y = pk2(bres(x.z), bres(x.w));
        dh[i] = hi;
        dl[i] = lo;
    }
}

__global__ void conv_w(const float* __restrict__ Wq, const float* __restrict__ Wk,
                       const float* __restrict__ Wv, const float* __restrict__ Wo)
{
    __shared__ float t[32][33];
    const int z = blockIdx.z;
    const float* W = (z == 0) ? Wq : (z == 1) ? Wk : (z == 2) ? Wv : Wo;
    __nv_bfloat16* th = g_wth[z];
    __nv_bfloat16* tl = g_wtl[z];
    const int nb = blockIdx.x * 32, kb = blockIdx.y * 32;
    const int tx = threadIdx.x, ty = threadIdx.y;
#pragma unroll
    for (int j = 0; j < 4; ++j)
        t[ty + 8 * j][tx] = W[(size_t)(kb + ty + 8 * j) * NN + nb + tx];
    __syncthreads();
#pragma unroll
    for (int j = 0; j < 4; ++j) {
        const float val = t[tx][ty + 8 * j];
        const size_t o = (size_t)(nb + ty + 8 * j) * KK + kb + tx;
        __nv_bfloat16 h = __float2bfloat16(val);
        th[o] = h;
        tl[o] = __float2bfloat16(val - __bfloat162float(h));
    }
}

// ===========================================================================
// cp.async bf16 split GEMM core: 128(M) x 64(N), BK=32, 256 threads,
// 8 warps (4m x 2n, warp 32x32). 3 stages x 24KB = 72KB DYNAMIC smem,
// prefetch depth 2. A, B already bf16 hi/lo in global (B transposed [n][k]).
// ===========================================================================
constexpr int BM = 128, BN = 64, BK = 32;
constexpr int STGB = 24576;
constexpr int AHI = 0, ALO = 8192, BHI = 16384, BLO = 20480;
constexpr int NT = KK / BK;
constexpr int GEMM_DSMEM  = 3 * STGB;      // 73728
constexpr int FLASH_DSMEM = 16384 + 2 * 32768;  // 81920

__device__ __forceinline__ void gemm_issue(uint64_t Ah, uint64_t Al,
                                           uint64_t Bh, uint64_t Bl,
                                           int k0, int tid, uint32_t stg)
{
    const int r = tid >> 2, c = tid & 3;
    const uint64_t ko = (uint64_t)(k0 + c * 8) * 2;
    const uint64_t so  = (uint64_t)r * (KK * 2) + ko;
    const uint64_t so2 = (uint64_t)(r + 64) * (KK * 2) + ko;
    const int sw  = sw_off(r, c);
    const int sw2 = sw_off(r + 64, c);
    CP16(stg + AHI + sw,  Ah + so);
    CP16(stg + ALO + sw,  Al + so);
    CP16(stg + AHI + sw2, Ah + so2);
    CP16(stg + ALO + sw2, Al + so2);
    CP16(stg + BHI + sw,  Bh + so);
    CP16(stg + BLO + sw,  Bl + so);
}

__device__ __forceinline__ void gemm_core(uint64_t Ah, uint64_t Al,
                                          uint64_t Bh, uint64_t Bl,
                                          int m0, int n0, int lane,
                                          float acc[2][4][4])
{
    extern __shared__ __align__(128) char dynsm[];
    const uint32_t sbase = smem_u32(dynsm);
    const int tid = threadIdx.x;

#pragma unroll
    for (int mt = 0; mt < 2; ++mt)
#pragma unroll
        for (int nt = 0; nt < 4; ++nt)
#pragma unroll
            for (int i = 0; i < 4; ++i) acc[mt][nt][i] = 0.f;

    gemm_issue(Ah, Al, Bh, Bl, 0,  tid, sbase);
    CP_COMMIT();
    gemm_issue(Ah, Al, Bh, Bl, BK, tid, sbase + STGB);
    CP_COMMIT();

    int s_cur = 0, s_pf = 2;
    for (int t = 0; t < NT; ++t) {
        if (t + 2 < NT) {
            gemm_issue(Ah, Al, Bh, Bl, (t + 2) * BK, tid, sbase + s_pf * STGB);
            CP_COMMIT();
            CP_WAIT2();
            s_pf = (s_pf == 2) ? 0 : s_pf + 1;
        } else if (t + 1 < NT) {
            CP_WAIT1();
        } else {
            CP_WAIT0();
        }
        __syncthreads();

        const uint32_t sA = sbase + s_cur * STGB;
        const uint32_t sB = sA + BHI;
#pragma unroll
        for (int ks = 0; ks < 2; ++ks) {
            uint32_t ah[2][4], al[2][4], bh2[4][2], bl2[4][2];
#pragma unroll
            for (int mt = 0; mt < 2; ++mt) {
                const int row = m0 + mt * 16 + (lane & 15);
                const int ch  = ks * 2 + (lane >> 4);
                const uint32_t ad = sA + sw_off(row, ch);
                LDMX4(ah[mt], ad);
                LDMX4(al[mt], ad + ALO);
            }
#pragma unroll
            for (int np = 0; np < 2; ++np) {
                const int nr = n0 + np * 16 + ((lane >> 4) << 3) + (lane & 7);
                const int ch = ks * 2 + ((lane >> 3) & 1);
                const uint32_t ad = sB + sw_off(nr, ch);
                uint32_t th[4], tl[4];
                LDMX4(th, ad);
                LDMX4(tl, ad + (BLO - BHI));
                bh2[np * 2][0] = th[0]; bh2[np * 2][1] = th[1];
                bh2[np * 2 + 1][0] = th[2]; bh2[np * 2 + 1][1] = th[3];
                bl2[np * 2][0] = tl[0]; bl2[np * 2][1] = tl[1];
                bl2[np * 2 + 1][0] = tl[2]; bl2[np * 2 + 1][1] = tl[3];
            }
#pragma unroll
            for (int mt = 0; mt < 2; ++mt)
#pragma unroll
                for (int nt = 0; nt < 4; ++nt) {
                    MMA_BF16(acc[mt][nt], ah[mt], bh2[nt]);
                    MMA_BF16(acc[mt][nt], ah[mt], bl2[nt]);
                    MMA_BF16(acc[mt][nt], al[mt], bh2[nt]);
                }
        }
        __syncthreads();
        s_cur = (s_cur == 2) ? 0 : s_cur + 1;
    }
}

// QKV projection: writes bf16 hi/lo outputs for flash
__global__ __launch_bounds__(256, 2)
void qkv_v3(const float* __restrict__ bq, const float* __restrict__ bk,
            const float* __restrict__ bv)
{
    const int z = blockIdx.z;
    const float* bias = (z == 0) ? bq : (z == 1) ? bk : bv;
    const int tid = threadIdx.x, lane = tid & 31, w = tid >> 5;
    const int m0 = (w >> 1) * 32, n0 = (w & 1) * 32;
    const int bm = blockIdx.y * BM, bn = blockIdx.x * BN;

    const uint64_t Ah = gaddr(g_xh[z])  + (uint64_t)bm * KK * 2;
    const uint64_t Al = gaddr(g_xl[z])  + (uint64_t)bm * KK * 2;
    const uint64_t Bh = gaddr(g_wth[z]) + (uint64_t)bn * KK * 2;
    const uint64_t Bl = gaddr(g_wtl[z]) + (uint64_t)bn * KK * 2;

    float acc[2][4][4];
    gemm_core(Ah, Al, Bh, Bl, m0, n0, lane, acc);

    __nv_bfloat16* Yh = g_oh[z];
    __nv_bfloat16* Yl = g_ol[z];
#pragma unroll
    for (int nt = 0; nt < 4; ++nt) {
        const int gc = bn + n0 + nt * 8 + (lane & 3) * 2;
        const float b0 = bias[gc], b1 = bias[gc + 1];
#pragma unroll
        for (int mt = 0; mt < 2; ++mt) {
            const int gr = bm + m0 + mt * 16 + (lane >> 2);
            const float y0 = acc[mt][nt][0] + b0;
            const float y1 = acc[mt][nt][1] + b1;
            const float y2 = acc[mt][nt][2] + b0;
            const float y3 = acc[mt][nt][3] + b1;
            *(uint32_t*)&Yh[(size_t)gr * NN + gc]       = pk2(y0, y1);
            *(uint32_t*)&Yl[(size_t)gr * NN + gc]       = pk2(bres(y0), bres(y1));
            *(uint32_t*)&Yh[(size_t)(gr + 8) * NN + gc] = pk2(y2, y3);
            *(uint32_t*)&Yl[(size_t)(gr + 8) * NN + gc] = pk2(bres(y2), bres(y3));
        }
    }
}

// Output projection: A = attention output (bf16 hi/lo), fp32 out, q_mask
__global__ __launch_bounds__(256, 2)
void out_v3(const float* __restrict__ bo, float* __restrict__ out,
            const int* __restrict__ qmask)
{
    const int tid = threadIdx.x, lane = tid & 31, w = tid >> 5;
    const int m0 = (w >> 1) * 32, n0 = (w & 1) * 32;
    const int bm = blockIdx.y * BM, bn = blockIdx.x * BN;

    const uint64_t Ah = gaddr(g_ath)    + (uint64_t)bm * KK * 2;
    const uint64_t Al = gaddr(g_atl)    + (uint64_t)bm * KK * 2;
    const uint64_t Bh = gaddr(g_wth[3]) + (uint64_t)bn * KK * 2;
    const uint64_t Bl = gaddr(g_wtl[3]) + (uint64_t)bn * KK * 2;

    float acc[2][4][4];
    gemm_core(Ah, Al, Bh, Bl, m0, n0, lane, acc);

#pragma unroll
    for (int nt = 0; nt < 4; ++nt) {
        const int gc = bn + n0 + nt * 8 + (lane & 3) * 2;
        const float b0 = bo[gc], b1 = bo[gc + 1];
#pragma unroll
        for (int mt = 0; mt < 2; ++mt) {
            const int gr = bm + m0 + mt * 16 + (lane >> 2);
            const float s0 = (float)qmask[gr];
            const float s1 = (float)qmask[gr + 8];
            float2 v0, v1;
            v0.x = (acc[mt][nt][0] + b0) * s0;
            v0.y = (acc[mt][nt][1] + b1) * s0;
            v1.x = (acc[mt][nt][2] + b0) * s1;
            v1.y = (acc[mt][nt][3] + b1) * s1;
            *(float2*)(out + (size_t)gr * NN + gc)       = v0;
            *(float2*)(out + (size_t)(gr + 8) * NN + gc) = v1;
        }
    }
}

// ===========================================================================
// Flash attention v3: 128 q-rows/CTA, 8 warps, 256 threads, grid (8, 64).
// DYNAMIC 80KB: QB 16KB (two-phase hi->lo, prologue only) + 2 KV stages
// of 32KB (K hi/lo + V hi/lo), double-buffered with cp.async prefetch.
// Masking semantics identical to reference (additive -1e12 fp32 + quirk).
// ===========================================================================
constexpr int FQB = 0, FSTG0 = 16384, FSTGB = 32768;
constexpr int FKL_O = 8192, FVH_O = 16384, FVL_O = 24576;  // within stage

__device__ __forceinline__ void flash_issue(uint64_t Kh, uint64_t Kl,
                                            uint64_t Vh, uint64_t Vl,
                                            int b, int t, int hc, int tid,
                                            uint32_t stg)
{
#pragma unroll
    for (int i = 0; i < 2; ++i) {
        const int id = tid + i * 256;
        const int r = id >> 3, c = id & 7;
        const uint64_t off = ((uint64_t)(b * S + t * 64 + r) * NN + hc + c * 8) * 2;
        const int sw = fsw(r, c);
        CP16(stg + sw,         Kh + off);
        CP16(stg + FKL_O + sw, Kl + off);
        CP16(stg + FVH_O + sw, Vh + off);
        CP16(stg + FVL_O + sw, Vl + off);
    }
}

__global__ __launch_bounds__(256, 2)
void flash_v3(const int* __restrict__ v_mask)
{
    extern __shared__ __align__(128) char dynsm[];
    const uint32_t sb = smem_u32(dynsm);
    const int tid  = threadIdx.x;
    const int lane = tid & 31;
    const int w    = tid >> 5;         // 0..7
    const int m0   = w * 16;           // 0..112
    const int bh   = blockIdx.y;
    const int b    = bh >> 4;
    const int h    = bh & 15;
    const int q0   = blockIdx.x * 128;
    const int hc   = h * 64;

    const uint64_t Qh = gaddr(g_oh[0]);
    const uint64_t Ql = gaddr(g_ol[0]);
    const uint64_t Kh = gaddr(g_oh[1]);
    const uint64_t Kl = gaddr(g_ol[1]);
    const uint64_t Vh = gaddr(g_oh[2]);
    const uint64_t Vl = gaddr(g_ol[2]);

    // ---- Q phase 1: hi into QB, read frags ----
    uint32_t qh[4][4], ql[4][4];
    {
#pragma unroll
        for (int i = 0; i < 4; ++i) {
            const int id = tid + i * 256;
            const int r = id >> 3, c = id & 7;
            CP16(sb + FQB + fsw(r, c),
                 Qh + ((uint64_t)(b * S + q0 + r) * NN + hc + c * 8) * 2);
        }
        CP_COMMIT(); CP_WAIT0();
    }
    __syncthreads();
#pragma unroll
    for (int ks = 0; ks < 4; ++ks) {
        const int row = m0 + (lane & 15);
        const int ch  = ks * 2 + (lane >> 4);
        LDMX4(qh[ks], sb + FQB + fsw(row, ch));
    }
    __syncthreads();
    // ---- Q phase 2: lo into QB (reuse), read frags ----
    {
#pragma unroll
        for (int i = 0; i < 4; ++i) {
            const int id = tid + i * 256;
            const int r = id >> 3, c = id & 7;
            CP16(sb + FQB + fsw(r, c),
                 Ql + ((uint64_t)(b * S + q0 + r) * NN + hc + c * 8) * 2);
        }
        CP_COMMIT(); CP_WAIT0();
    }
    __syncthreads();
#pragma unroll
    for (int ks = 0; ks < 4; ++ks) {
        const int row = m0 + (lane & 15);
        const int ch  = ks * 2 + (lane >> 4);
        LDMX4(ql[ks], sb + FQB + fsw(row, ch));
    }

    const float NEGINF = __int_as_float(0xff800000);
    float m_[2] = {NEGINF, NEGINF};
    float l_[2] = {0.f, 0.f};
    float o[8][4];
#pragma unroll
    for (int nt = 0; nt < 8; ++nt)
#pragma unroll
        for (int i = 0; i < 4; ++i) o[nt][i] = 0.f;

    const int diag2 = 2 * blockIdx.x + 1;   // last causal-needed tile

    // prefetch KV tile 0 -> stage 0
    flash_issue(Kh, Kl, Vh, Vl, b, 0, hc, tid, sb + FSTG0);
    CP_COMMIT();

    for (int t = 0; t < 16; ++t) {
        __syncthreads();   // stage (t+1)&1 fully read (iter t-1)
        if (t + 1 < 16) {
            flash_issue(Kh, Kl, Vh, Vl, b, t + 1, hc, tid,
                        sb + FSTG0 + ((t + 1) & 1) * FSTGB);
            CP_COMMIT();
            CP_WAIT1();
        } else {
            CP_WAIT0();
        }
        __syncthreads();   // tile t's data visible to all

        const uint32_t sK = sb + FSTG0 + (t & 1) * FSTGB;
        const uint32_t sV = sK + FVH_O;

        // ---- S = Q K^T (split-bf16, 3 passes) ----
        float sc[8][4];
#pragma unroll
        for (int nt = 0; nt < 8; ++nt)
#pragma unroll
            for (int i = 0; i < 4; ++i) sc[nt][i] = 0.f;
#pragma unroll
        for (int ks = 0; ks < 4; ++ks) {
            uint32_t kbh[8][2], kbl[8][2];
#pragma unroll
            for (int np = 0; np < 4; ++np) {
                const int nr = np * 16 + ((lane >> 4) << 3) + (lane & 7);
                const int ch = ks * 2 + ((lane >> 3) & 1);
                const uint32_t ad = sK + fsw(nr, ch);
                uint32_t th[4], tl[4];
                LDMX4(th, ad);
                LDMX4(tl, ad + FKL_O);
                kbh[np * 2][0] = th[0]; kbh[np * 2][1] = th[1];
                kbh[np * 2 + 1][0] = th[2]; kbh[np * 2 + 1][1] = th[3];
                kbl[np * 2][0] = tl[0]; kbl[np * 2][1] = tl[1];
                kbl[np * 2 + 1][0] = tl[2]; kbl[np * 2 + 1][1] = tl[3];
            }
#pragma unroll
            for (int nt = 0; nt < 8; ++nt) {
                MMA_BF16(sc[nt], qh[ks], kbh[nt]);
                MMA_BF16(sc[nt], qh[ks], kbl[nt]);
                MMA_BF16(sc[nt], ql[ks], kbh[nt]);
            }
        }

        // ---- mask + online softmax (v_mask from global/L1) ----
        const int r0g = q0 + m0 + (lane >> 2);
        const int r1g = r0g + 8;
        const int vmb = b * S + t * 64;
        float tmax0 = NEGINF, tmax1 = NEGINF;
#pragma unroll
        for (int nt = 0; nt < 8; ++nt) {
            const int c0  = nt * 8 + (lane & 3) * 2;
            const int cg0 = t * 64 + c0;
            const float p0 = (1.0f - (float)__ldg(&v_mask[vmb + c0]))     * 1e12f;
            const float p1 = (1.0f - (float)__ldg(&v_mask[vmb + c0 + 1])) * 1e12f;
            float s0 = sc[nt][0] * 0.125f - p0; if (cg0     > r0g) s0 -= 1e12f;
            float s1 = sc[nt][1] * 0.125f - p1; if (cg0 + 1 > r0g) s1 -= 1e12f;
            float s2 = sc[nt][2] * 0.125f - p0; if (cg0     > r1g) s2 -= 1e12f;
            float s3 = sc[nt][3] * 0.125f - p1; if (cg0 + 1 > r1g) s3 -= 1e12f;
            sc[nt][0] = s0; sc[nt][1] = s1; sc[nt][2] = s2; sc[nt][3] = s3;
            tmax0 = fmaxf(tmax0, fmaxf(s0, s1));
            tmax1 = fmaxf(tmax1, fmaxf(s2, s3));
        }
        tmax0 = fmaxf(tmax0, __shfl_xor_sync(0xffffffffu, tmax0, 1));
        tmax0 = fmaxf(tmax0, __shfl_xor_sync(0xffffffffu, tmax0, 2));
        tmax1 = fmaxf(tmax1, __shfl_xor_sync(0xffffffffu, tmax1, 1));
        tmax1 = fmaxf(tmax1, __shfl_xor_sync(0xffffffffu, tmax1, 2));
        const float mn0 = fmaxf(m_[0], tmax0);
        const float mn1 = fmaxf(m_[1], tmax1);
        const float al0 = __expf(m_[0] - mn0);
        const float al1 = __expf(m_[1] - mn1);
        float rs0 = 0.f, rs1 = 0.f;
#pragma unroll
        for (int nt = 0; nt < 8; ++nt) {
            sc[nt][0] = __expf(sc[nt][0] - mn0); rs0 += sc[nt][0];
            sc[nt][1] = __expf(sc[nt][1] - mn0); rs0 += sc[nt][1];
            sc[nt][2] = __expf(sc[nt][2] - mn1); rs1 += sc[nt][2];
            sc[nt][3] = __expf(sc[nt][3] - mn1); rs1 += sc[nt][3];
        }
        rs0 += __shfl_xor_sync(0xffffffffu, rs0, 1);
        rs0 += __shfl_xor_sync(0xffffffffu, rs0, 2);
        rs1 += __shfl_xor_sync(0xffffffffu, rs1, 1);
        rs1 += __shfl_xor_sync(0xffffffffu, rs1, 2);
        l_[0] = l_[0] * al0 + rs0;
        l_[1] = l_[1] * al1 + rs1;
        m_[0] = mn0;
        m_[1] = mn1;
#pragma unroll
        for (int nt = 0; nt < 8; ++nt) {
            o[nt][0] *= al0; o[nt][1] *= al0;
            o[nt][2] *= al1; o[nt][3] *= al1;
        }

        // ---- O += P V (P repacked in registers; V via ldmatrix.trans) ----
#pragma unroll
        for (int kt = 0; kt < 4; ++kt) {
            uint32_t pah[4], pal[4];
            pah[0] = pk2(sc[2 * kt][0],     sc[2 * kt][1]);
            pah[1] = pk2(sc[2 * kt][2],     sc[2 * kt][3]);
            pah[2] = pk2(sc[2 * kt + 1][0], sc[2 * kt + 1][1]);
            pah[3] = pk2(sc[2 * kt + 1][2], sc[2 * kt + 1][3]);
            pal[0] = pk2(bres(sc[2 * kt][0]),     bres(sc[2 * kt][1]));
            pal[1] = pk2(bres(sc[2 * kt][2]),     bres(sc[2 * kt][3]));
            pal[2] = pk2(bres(sc[2 * kt + 1][0]), bres(sc[2 * kt + 1][1]));
            pal[3] = pk2(bres(sc[2 * kt + 1][2]), bres(sc[2 * kt + 1][3]));
#pragma unroll
            for (int np = 0; np < 4; ++np) {
                const int key = kt * 16 + (lane & 7) + ((lane >> 3) & 1) * 8;
                const int ch  = np * 2 + (lane >> 4);
                const uint32_t ad = sV + fsw(key, ch);
                uint32_t vh4[4], vl4[4];
                LDMX4T(vh4, ad);
                LDMX4T(vl4, ad + (FVL_O - FVH_O));
                uint32_t vb0h[2] = {vh4[0], vh4[1]}, vb1h[2] = {vh4[2], vh4[3]};
                uint32_t vb0l[2] = {vl4[0], vl4[1]}, vb1l[2] = {vl4[2], vl4[3]};
                MMA_BF16(o[np * 2],     pah, vb0h);
                MMA_BF16(o[np * 2],     pah, vb0l);
                MMA_BF16(o[np * 2],     pal, vb0h);
                MMA_BF16(o[np * 2 + 1], pah, vb1h);
                MMA_BF16(o[np * 2 + 1], pah, vb1l);
                MMA_BF16(o[np * 2 + 1], pal, vb1h);
            }
        }

        // Past diagonal: continue only while some row is still fully masked
        if (t >= diag2) {
            int pred = (mn0 <= -1e11f) | (mn1 <= -1e11f);
            if (!__syncthreads_or(pred)) break;
        }
    }

    // ---- normalize + store as bf16 hi/lo for the output projection ----
    const float inv0 = 1.0f / l_[0];
    const float inv1 = 1.0f / l_[1];
    const int gr0 = b * S + q0 + m0 + (lane >> 2);
#pragma unroll
    for (int nt = 0; nt < 8; ++nt) {
        const int col = hc + nt * 8 + (lane & 3) * 2;
        const float a0 = o[nt][0] * inv0, a1 = o[nt][1] * inv0;
        const float a2 = o[nt][2] * inv1, a3 = o[nt][3] * inv1;
        *(uint32_t*)&g_ath[(size_t)gr0 * NN + col]       = pk2(a0, a1);
        *(uint32_t*)&g_atl[(size_t)gr0 * NN + col]       = pk2(bres(a0), bres(a1));
        *(uint32_t*)&g_ath[(size_t)(gr0 + 8) * NN + col] = pk2(a2, a3);
        *(uint32_t*)&g_atl[(size_t)(gr0 + 8) * NN + col] = pk2(bres(a2), bres(a3));
    }
}

// ---------------------------------------------------------------------------
extern "C" void kernel_launch(void* const* d_in, const int* in_sizes, int n_in,
                              void* d_out, int out_size)
{
    (void)in_sizes; (void)n_in; (void)out_size;
    const float* q     = (const float*)d_in[0];
    const float* k     = (const float*)d_in[1];
    const float* v     = (const float*)d_in[2];
    const int*   vmask = (const int*)  d_in[3];
    const int*   qmask = (const int*)  d_in[4];
    const float* Wq = (const float*)d_in[6];
    const float* bq = (const float*)d_in[7];
    const float* Wk = (const float*)d_in[8];
    const float* bk = (const float*)d_in[9];
    const float* Wv = (const float*)d_in[10];
    const float* bv = (const float*)d_in[11];
    const float* Wo = (const float*)d_in[12];
    const float* bo = (const float*)d_in[13];
    float* out = (float*)d_out;

    // Capture-legal (no allocation, no enqueue); idempotent per call.
    cudaFuncSetAttribute(qkv_v3,
        cudaFuncAttributeMaxDynamicSharedMemorySize, GEMM_DSMEM);
    cudaFuncSetAttribute(out_v3,
        cudaFuncAttributeMaxDynamicSharedMemorySize, GEMM_DSMEM);
    cudaFuncSetAttribute(flash_v3,
        cudaFuncAttributeMaxDynamicSharedMemorySize, FLASH_DSMEM);

    conv_in<<<dim3(1024, 1, 3), 256>>>(q, k, v);
    conv_w<<<dim3(32, 32, 4), dim3(32, 8)>>>(Wq, Wk, Wv, Wo);
    qkv_v3<<<dim3(NN / BN, M / BM, 3), 256, GEMM_DSMEM>>>(bq, bk, bv);
    flash_v3<<<dim3(S / 128, B * H), 256, FLASH_DSMEM>>>(vmask);
    out_v3<<<dim3(NN / BN, M / BM), 256, GEMM_DSMEM>>>(bo, out, qmask);
}

// round 13
// speedup vs baseline: 2.9021x; 1.0480x over previous
#include <cuda_runtime.h>
#include <cuda_bf16.h>
#include <math.h>
#include <stdint.h>

// Problem constants
constexpr int B  = 4;
constexpr int S  = 1024;
constexpr int H  = 16;
constexpr int M  = B * S;          // 4096
constexpr int NN = H * 64;         // 1024
constexpr int KK = 1024;

// ===========================================================================
// Global scratch (device globals: allocation-free). bf16 hi/lo dataflow.
// ===========================================================================
__device__ __nv_bfloat16 g_xh[3][(size_t)M * KK];   // converted inputs q,k,v
__device__ __nv_bfloat16 g_xl[3][(size_t)M * KK];
__device__ __nv_bfloat16 g_wth[4][(size_t)NN * KK]; // transposed weights [n][k]
__device__ __nv_bfloat16 g_wtl[4][(size_t)NN * KK];
__device__ __nv_bfloat16 g_oh[3][(size_t)M * NN];   // qw,kw,vw (proj outputs)
__device__ __nv_bfloat16 g_ol[3][(size_t)M * NN];
__device__ __nv_bfloat16 g_ath[(size_t)M * NN];     // attention output
__device__ __nv_bfloat16 g_atl[(size_t)M * NN];

// ===========================================================================
// Helpers
// ===========================================================================
__device__ __forceinline__ uint32_t smem_u32(const void* p) {
    uint32_t a;
    asm("{ .reg .u64 t; cvta.to.shared.u64 t, %1; cvt.u32.u64 %0, t; }"
        : "=r"(a) : "l"(p));
    return a;
}
__device__ __forceinline__ uint64_t gaddr(const void* p) {
    uint64_t r;
    asm("cvta.to.global.u64 %0, %1;" : "=l"(r) : "l"(p));
    return r;
}
__device__ __forceinline__ uint32_t pk2(float a, float b) {
    __nv_bfloat162 t;
    t.x = __float2bfloat16(a);
    t.y = __float2bfloat16(b);
    return *(uint32_t*)&t;
}
__device__ __forceinline__ float bres(float x) {   // residual after bf16 hi
    __nv_bfloat16 h = __float2bfloat16(x);
    return x - __bfloat162float(h);
}

// 64B-row swizzle (GEMM tiles: 32 bf16 per row), chunk 0..3
__device__ __forceinline__ int sw_off(int row, int chunk) {
    return row * 64 + ((chunk ^ ((row >> 1) & 3) ^ ((row >> 3) & 3)) << 4);
}
// 128B-row swizzle (flash tiles: 64 bf16 per row), chunk 0..7
__device__ __forceinline__ int fsw(int row, int chunk) {
    return row * 128 + ((chunk ^ (row & 7)) << 4);
}

#define LDMX4(r, addr) \
    asm volatile("ldmatrix.sync.aligned.m8n8.x4.shared.b16 {%0,%1,%2,%3}, [%4];" \
        : "=r"((r)[0]), "=r"((r)[1]), "=r"((r)[2]), "=r"((r)[3]) : "r"(addr))
#define LDMX4T(r, addr) \
    asm volatile("ldmatrix.sync.aligned.m8n8.x4.trans.shared.b16 {%0,%1,%2,%3}, [%4];" \
        : "=r"((r)[0]), "=r"((r)[1]), "=r"((r)[2]), "=r"((r)[3]) : "r"(addr))
#define MMA_BF16(d, a, bb) \
    asm volatile("mma.sync.aligned.m16n8k16.row.col.f32.bf16.bf16.f32 " \
        "{%0,%1,%2,%3}, {%4,%5,%6,%7}, {%8,%9}, {%0,%1,%2,%3};" \
        : "+f"((d)[0]), "+f"((d)[1]), "+f"((d)[2]), "+f"((d)[3]) \
        : "r"((a)[0]), "r"((a)[1]), "r"((a)[2]), "r"((a)[3]), \
          "r"((bb)[0]), "r"((bb)[1]))
#define CP16(dst, src) \
    asm volatile("cp.async.cg.shared.global [%0], [%1], 16;" \
        :: "r"((uint32_t)(dst)), "l"((uint64_t)(src)))
#define CP_COMMIT() asm volatile("cp.async.commit_group;" ::: "memory")
#define CP_WAIT0()  asm volatile("cp.async.wait_group 0;" ::: "memory")
#define CP_WAIT1()  asm volatile("cp.async.wait_group 1;" ::: "memory")
#define CP_WAIT2()  asm volatile("cp.async.wait_group 2;" ::: "memory")

// ===========================================================================
// Merged conversion kernel (z 0..2: inputs, z 3..6: transposed weights)
// ===========================================================================
__global__ void conv_all(const float* __restrict__ q,
                         const float* __restrict__ k,
                         const float* __restrict__ v,
                         const float* __restrict__ Wq,
                         const float* __restrict__ Wk,
                         const float* __restrict__ Wv,
                         const float* __restrict__ Wo)
{
    const int z = blockIdx.z;
    if (z < 3) {
        const float* src = (z == 0) ? q : (z == 1) ? k : v;
        uint2* dh = (uint2*)g_xh[z];
        uint2* dl = (uint2*)g_xl[z];
        const int n4 = M * KK / 4;
        for (int i = blockIdx.x * blockDim.x + threadIdx.x; i < n4;
             i += gridDim.x * blockDim.x) {
            float4 x = ((const float4*)src)[i];
            uint2 hi, lo;
            hi.x = pk2(x.x, x.y);             hi.y = pk2(x.z, x.w);
            lo.x = pk2(bres(x.x), bres(x.y)); lo.y = pk2(bres(x.z), bres(x.w));
            dh[i] = hi;
            dl[i] = lo;
        }
    } else {
        __shared__ float t[32][33];
        const int zw = z - 3;
        const float* W = (zw == 0) ? Wq : (zw == 1) ? Wk : (zw == 2) ? Wv : Wo;
        __nv_bfloat16* th = g_wth[zw];
        __nv_bfloat16* tl = g_wtl[zw];
        const int nb = (blockIdx.x & 31) * 32;
        const int kb = (blockIdx.x >> 5) * 32;
        const int tx = threadIdx.x & 31, ty = threadIdx.x >> 5;  // ty 0..7
#pragma unroll
        for (int j = 0; j < 4; ++j)
            t[ty + 8 * j][tx] = W[(size_t)(kb + ty + 8 * j) * NN + nb + tx];
        __syncthreads();
#pragma unroll
        for (int j = 0; j < 4; ++j) {
            const float val = t[tx][ty + 8 * j];
            const size_t o = (size_t)(nb + ty + 8 * j) * KK + kb + tx;
            __nv_bfloat16 h = __float2bfloat16(val);
            th[o] = h;
            tl[o] = __float2bfloat16(val - __bfloat162float(h));
        }
    }
}

// ===========================================================================
// cp.async bf16 split GEMM core: 128(M) x 64(N), BK=32, 256 threads,
// 8 warps (4m x 2n, warp 32x32). 4 stages x 24KB = 96KB DYNAMIC smem,
// prefetch depth 2, ONE __syncthreads per k-iter.
// Hazard proof: at iter t the fastest warp writes stage (t+2)&3; the slowest
// warp (past sync(t-1)) reads stage (t-1)&3 — distinct mod 4.
// ===========================================================================
constexpr int BM = 128, BN = 64, BK = 32;
constexpr int STGB = 24576;
constexpr int AHI = 0, ALO = 8192, BHI = 16384, BLO = 20480;
constexpr int NT = KK / BK;
constexpr int GEMM_DSMEM  = 4 * STGB;            // 98304
constexpr int FLASH_DSMEM = 16384 + 3 * 32768;   // 114688

__device__ __forceinline__ void gemm_issue(uint64_t Ah, uint64_t Al,
                                           uint64_t Bh, uint64_t Bl,
                                           int k0, int tid, uint32_t stg)
{
    const int r = tid >> 2, c = tid & 3;
    const uint64_t ko = (uint64_t)(k0 + c * 8) * 2;
    const uint64_t so  = (uint64_t)r * (KK * 2) + ko;
    const uint64_t so2 = (uint64_t)(r + 64) * (KK * 2) + ko;
    const int sw  = sw_off(r, c);
    const int sw2 = sw_off(r + 64, c);
    CP16(stg + AHI + sw,  Ah + so);
    CP16(stg + ALO + sw,  Al + so);
    CP16(stg + AHI + sw2, Ah + so2);
    CP16(stg + ALO + sw2, Al + so2);
    CP16(stg + BHI + sw,  Bh + so);
    CP16(stg + BLO + sw,  Bl + so);
}

__device__ __forceinline__ void gemm_core(uint64_t Ah, uint64_t Al,
                                          uint64_t Bh, uint64_t Bl,
                                          int m0, int n0, int lane,
                                          float acc[2][4][4])
{
    extern __shared__ __align__(128) char dynsm[];
    const uint32_t sbase = smem_u32(dynsm);
    const int tid = threadIdx.x;

#pragma unroll
    for (int mt = 0; mt < 2; ++mt)
#pragma unroll
        for (int nt = 0; nt < 4; ++nt)
#pragma unroll
            for (int i = 0; i < 4; ++i) acc[mt][nt][i] = 0.f;

    gemm_issue(Ah, Al, Bh, Bl, 0,  tid, sbase);
    CP_COMMIT();
    gemm_issue(Ah, Al, Bh, Bl, BK, tid, sbase + STGB);
    CP_COMMIT();

    for (int t = 0; t < NT; ++t) {
        if (t + 2 < NT) {
            gemm_issue(Ah, Al, Bh, Bl, (t + 2) * BK, tid,
                       sbase + ((t + 2) & 3) * STGB);
            CP_COMMIT();
            CP_WAIT2();
        } else if (t + 1 < NT) {
            CP_WAIT1();
        } else {
            CP_WAIT0();
        }
        __syncthreads();

        const uint32_t sA = sbase + (t & 3) * STGB;
        const uint32_t sB = sA + BHI;
#pragma unroll
        for (int ks = 0; ks < 2; ++ks) {
            uint32_t ah[2][4], al[2][4], bh2[4][2], bl2[4][2];
#pragma unroll
            for (int mt = 0; mt < 2; ++mt) {
                const int row = m0 + mt * 16 + (lane & 15);
                const int ch  = ks * 2 + (lane >> 4);
                const uint32_t ad = sA + sw_off(row, ch);
                LDMX4(ah[mt], ad);
                LDMX4(al[mt], ad + ALO);
            }
#pragma unroll
            for (int np = 0; np < 2; ++np) {
                const int nr = n0 + np * 16 + ((lane >> 4) << 3) + (lane & 7);
                const int ch = ks * 2 + ((lane >> 3) & 1);
                const uint32_t ad = sB + sw_off(nr, ch);
                uint32_t th[4], tl[4];
                LDMX4(th, ad);
                LDMX4(tl, ad + (BLO - BHI));
                bh2[np * 2][0] = th[0]; bh2[np * 2][1] = th[1];
                bh2[np * 2 + 1][0] = th[2]; bh2[np * 2 + 1][1] = th[3];
                bl2[np * 2][0] = tl[0]; bl2[np * 2][1] = tl[1];
                bl2[np * 2 + 1][0] = tl[2]; bl2[np * 2 + 1][1] = tl[3];
            }
#pragma unroll
            for (int mt = 0; mt < 2; ++mt)
#pragma unroll
                for (int nt = 0; nt < 4; ++nt) {
                    MMA_BF16(acc[mt][nt], ah[mt], bh2[nt]);
                    MMA_BF16(acc[mt][nt], ah[mt], bl2[nt]);
                    MMA_BF16(acc[mt][nt], al[mt], bh2[nt]);
                }
        }
        // no trailing sync: 4-stage rotation guarantees no write/read overlap
    }
}

// QKV projection: writes bf16 hi/lo outputs for flash
__global__ __launch_bounds__(256, 2)
void qkv_v4(const float* __restrict__ bq, const float* __restrict__ bk,
            const float* __restrict__ bv)
{
    const int z = blockIdx.z;
    const float* bias = (z == 0) ? bq : (z == 1) ? bk : bv;
    const int tid = threadIdx.x, lane = tid & 31, w = tid >> 5;
    const int m0 = (w >> 1) * 32, n0 = (w & 1) * 32;
    const int bm = blockIdx.y * BM, bn = blockIdx.x * BN;

    const uint64_t Ah = gaddr(g_xh[z])  + (uint64_t)bm * KK * 2;
    const uint64_t Al = gaddr(g_xl[z])  + (uint64_t)bm * KK * 2;
    const uint64_t Bh = gaddr(g_wth[z]) + (uint64_t)bn * KK * 2;
    const uint64_t Bl = gaddr(g_wtl[z]) + (uint64_t)bn * KK * 2;

    float acc[2][4][4];
    gemm_core(Ah, Al, Bh, Bl, m0, n0, lane, acc);

    __nv_bfloat16* Yh = g_oh[z];
    __nv_bfloat16* Yl = g_ol[z];
#pragma unroll
    for (int nt = 0; nt < 4; ++nt) {
        const int gc = bn + n0 + nt * 8 + (lane & 3) * 2;
        const float b0 = bias[gc], b1 = bias[gc + 1];
#pragma unroll
        for (int mt = 0; mt < 2; ++mt) {
            const int gr = bm + m0 + mt * 16 + (lane >> 2);
            const float y0 = acc[mt][nt][0] + b0;
            const float y1 = acc[mt][nt][1] + b1;
            const float y2 = acc[mt][nt][2] + b0;
            const float y3 = acc[mt][nt][3] + b1;
            *(uint32_t*)&Yh[(size_t)gr * NN + gc]       = pk2(y0, y1);
            *(uint32_t*)&Yl[(size_t)gr * NN + gc]       = pk2(bres(y0), bres(y1));
            *(uint32_t*)&Yh[(size_t)(gr + 8) * NN + gc] = pk2(y2, y3);
            *(uint32_t*)&Yl[(size_t)(gr + 8) * NN + gc] = pk2(bres(y2), bres(y3));
        }
    }
}

// Output projection: A = attention output (bf16 hi/lo), fp32 out, q_mask
__global__ __launch_bounds__(256, 2)
void out_v4(const float* __restrict__ bo, float* __restrict__ out,
            const int* __restrict__ qmask)
{
    const int tid = threadIdx.x, lane = tid & 31, w = tid >> 5;
    const int m0 = (w >> 1) * 32, n0 = (w & 1) * 32;
    const int bm = blockIdx.y * BM, bn = blockIdx.x * BN;

    const uint64_t Ah = gaddr(g_ath)    + (uint64_t)bm * KK * 2;
    const uint64_t Al = gaddr(g_atl)    + (uint64_t)bm * KK * 2;
    const uint64_t Bh = gaddr(g_wth[3]) + (uint64_t)bn * KK * 2;
    const uint64_t Bl = gaddr(g_wtl[3]) + (uint64_t)bn * KK * 2;

    float acc[2][4][4];
    gemm_core(Ah, Al, Bh, Bl, m0, n0, lane, acc);

#pragma unroll
    for (int nt = 0; nt < 4; ++nt) {
        const int gc = bn + n0 + nt * 8 + (lane & 3) * 2;
        const float b0 = bo[gc], b1 = bo[gc + 1];
#pragma unroll
        for (int mt = 0; mt < 2; ++mt) {
            const int gr = bm + m0 + mt * 16 + (lane >> 2);
            const float s0 = (float)qmask[gr];
            const float s1 = (float)qmask[gr + 8];
            float2 v0, v1;
            v0.x = (acc[mt][nt][0] + b0) * s0;
            v0.y = (acc[mt][nt][1] + b1) * s0;
            v1.x = (acc[mt][nt][2] + b0) * s1;
            v1.y = (acc[mt][nt][3] + b1) * s1;
            *(float2*)(out + (size_t)gr * NN + gc)       = v0;
            *(float2*)(out + (size_t)(gr + 8) * NN + gc) = v1;
        }
    }
}

// ===========================================================================
// Flash attention v4: 128 q-rows/CTA, 8 warps, 256 threads, grid (8, 64).
// DYNAMIC 112KB: QB 16KB (two-phase hi->lo, prologue only) + 3 KV stages
// of 32KB, cp.async prefetch depth 1, ONE __syncthreads per tile.
// Hazard proof: at tile t the fastest warp writes stage (t+1)%3; the slowest
// warp (past sync(t-1)) reads stage (t-1)%3 — distinct mod 3.
// Masking semantics identical to reference (additive -1e12 fp32 + quirk).
// ===========================================================================
constexpr int FQB = 0, FSTG0 = 16384, FSTGB = 32768;
constexpr int FKL_O = 8192, FVH_O = 16384, FVL_O = 24576;  // within stage

__device__ __forceinline__ void flash_issue(uint64_t Kh, uint64_t Kl,
                                            uint64_t Vh, uint64_t Vl,
                                            int b, int t, int hc, int tid,
                                            uint32_t stg)
{
#pragma unroll
    for (int i = 0; i < 2; ++i) {
        const int id = tid + i * 256;
        const int r = id >> 3, c = id & 7;
        const uint64_t off = ((uint64_t)(b * S + t * 64 + r) * NN + hc + c * 8) * 2;
        const int sw = fsw(r, c);
        CP16(stg + sw,         Kh + off);
        CP16(stg + FKL_O + sw, Kl + off);
        CP16(stg + FVH_O + sw, Vh + off);
        CP16(stg + FVL_O + sw, Vl + off);
    }
}

__global__ __launch_bounds__(256, 2)
void flash_v4(const int* __restrict__ v_mask)
{
    extern __shared__ __align__(128) char dynsm[];
    const uint32_t sb = smem_u32(dynsm);
    const int tid  = threadIdx.x;
    const int lane = tid & 31;
    const int w    = tid >> 5;         // 0..7
    const int m0   = w * 16;           // 0..112
    const int bh   = blockIdx.y;
    const int b    = bh >> 4;
    const int h    = bh & 15;
    const int q0   = blockIdx.x * 128;
    const int hc   = h * 64;

    const uint64_t Qh = gaddr(g_oh[0]);
    const uint64_t Ql = gaddr(g_ol[0]);
    const uint64_t Kh = gaddr(g_oh[1]);
    const uint64_t Kl = gaddr(g_ol[1]);
    const uint64_t Vh = gaddr(g_oh[2]);
    const uint64_t Vl = gaddr(g_ol[2]);

    // ---- Q phase 1: hi into QB, read frags ----
    uint32_t qh[4][4], ql[4][4];
    {
#pragma unroll
        for (int i = 0; i < 4; ++i) {
            const int id = tid + i * 256;
            const int r = id >> 3, c = id & 7;
            CP16(sb + FQB + fsw(r, c),
                 Qh + ((uint64_t)(b * S + q0 + r) * NN + hc + c * 8) * 2);
        }
        CP_COMMIT(); CP_WAIT0();
    }
    __syncthreads();
#pragma unroll
    for (int ks = 0; ks < 4; ++ks) {
        const int row = m0 + (lane & 15);
        const int ch  = ks * 2 + (lane >> 4);
        LDMX4(qh[ks], sb + FQB + fsw(row, ch));
    }
    __syncthreads();
    // ---- Q phase 2: lo into QB (reuse), read frags ----
    {
#pragma unroll
        for (int i = 0; i < 4; ++i) {
            const int id = tid + i * 256;
            const int r = id >> 3, c = id & 7;
            CP16(sb + FQB + fsw(r, c),
                 Ql + ((uint64_t)(b * S + q0 + r) * NN + hc + c * 8) * 2);
        }
        CP_COMMIT(); CP_WAIT0();
    }
    __syncthreads();
#pragma unroll
    for (int ks = 0; ks < 4; ++ks) {
        const int row = m0 + (lane & 15);
        const int ch  = ks * 2 + (lane >> 4);
        LDMX4(ql[ks], sb + FQB + fsw(row, ch));
    }

    const float NEGINF = __int_as_float(0xff800000);
    float m_[2] = {NEGINF, NEGINF};
    float l_[2] = {0.f, 0.f};
    float o[8][4];
#pragma unroll
    for (int nt = 0; nt < 8; ++nt)
#pragma unroll
        for (int i = 0; i < 4; ++i) o[nt][i] = 0.f;

    const int diag2 = 2 * blockIdx.x + 1;   // last causal-needed tile

    // prefetch KV tile 0 -> stage 0
    flash_issue(Kh, Kl, Vh, Vl, b, 0, hc, tid, sb + FSTG0);
    CP_COMMIT();

    int s_cur = 0, s_nxt = 1;
    for (int t = 0; t < 16; ++t) {
        if (t + 1 < 16) {
            flash_issue(Kh, Kl, Vh, Vl, b, t + 1, hc, tid,
                        sb + FSTG0 + s_nxt * FSTGB);
            CP_COMMIT();
            CP_WAIT1();
        } else {
            CP_WAIT0();
        }
        __syncthreads();   // single barrier: tile t visible; 3-stage rotation
                           // keeps writes (t+1) clear of slowest readers (t-1)

        const uint32_t sK = sb + FSTG0 + s_cur * FSTGB;
        const uint32_t sV = sK + FVH_O;

        // ---- S = Q K^T (split-bf16, 3 passes) ----
        float sc[8][4];
#pragma unroll
        for (int nt = 0; nt < 8; ++nt)
#pragma unroll
            for (int i = 0; i < 4; ++i) sc[nt][i] = 0.f;
#pragma unroll
        for (int ks = 0; ks < 4; ++ks) {
            uint32_t kbh[8][2], kbl[8][2];
#pragma unroll
            for (int np = 0; np < 4; ++np) {
                const int nr = np * 16 + ((lane >> 4) << 3) + (lane & 7);
                const int ch = ks * 2 + ((lane >> 3) & 1);
                const uint32_t ad = sK + fsw(nr, ch);
                uint32_t th[4], tl[4];
                LDMX4(th, ad);
                LDMX4(tl, ad + FKL_O);
                kbh[np * 2][0] = th[0]; kbh[np * 2][1] = th[1];
                kbh[np * 2 + 1][0] = th[2]; kbh[np * 2 + 1][1] = th[3];
                kbl[np * 2][0] = tl[0]; kbl[np * 2][1] = tl[1];
                kbl[np * 2 + 1][0] = tl[2]; kbl[np * 2 + 1][1] = tl[3];
            }
#pragma unroll
            for (int nt = 0; nt < 8; ++nt) {
                MMA_BF16(sc[nt], qh[ks], kbh[nt]);
                MMA_BF16(sc[nt], qh[ks], kbl[nt]);
                MMA_BF16(sc[nt], ql[ks], kbh[nt]);
            }
        }

        // ---- mask + online softmax (v_mask from global/L1) ----
        const int r0g = q0 + m0 + (lane >> 2);
        const int r1g = r0g + 8;
        const int vmb = b * S + t * 64;
        float tmax0 = NEGINF, tmax1 = NEGINF;
#pragma unroll
        for (int nt = 0; nt < 8; ++nt) {
            const int c0  = nt * 8 + (lane & 3) * 2;
            const int cg0 = t * 64 + c0;
            const float p0 = (1.0f - (float)__ldg(&v_mask[vmb + c0]))     * 1e12f;
            const float p1 = (1.0f - (float)__ldg(&v_mask[vmb + c0 + 1])) * 1e12f;
            float s0 = sc[nt][0] * 0.125f - p0; if (cg0     > r0g) s0 -= 1e12f;
            float s1 = sc[nt][1] * 0.125f - p1; if (cg0 + 1 > r0g) s1 -= 1e12f;
            float s2 = sc[nt][2] * 0.125f - p0; if (cg0     > r1g) s2 -= 1e12f;
            float s3 = sc[nt][3] * 0.125f - p1; if (cg0 + 1 > r1g) s3 -= 1e12f;
            sc[nt][0] = s0; sc[nt][1] = s1; sc[nt][2] = s2; sc[nt][3] = s3;
            tmax0 = fmaxf(tmax0, fmaxf(s0, s1));
            tmax1 = fmaxf(tmax1, fmaxf(s2, s3));
        }
        tmax0 = fmaxf(tmax0, __shfl_xor_sync(0xffffffffu, tmax0, 1));
        tmax0 = fmaxf(tmax0, __shfl_xor_sync(0xffffffffu, tmax0, 2));
        tmax1 = fmaxf(tmax1, __shfl_xor_sync(0xffffffffu, tmax1, 1));
        tmax1 = fmaxf(tmax1, __shfl_xor_sync(0xffffffffu, tmax1, 2));
        const float mn0 = fmaxf(m_[0], tmax0);
        const float mn1 = fmaxf(m_[1], tmax1);
        const float al0 = __expf(m_[0] - mn0);
        const float al1 = __expf(m_[1] - mn1);
        float rs0 = 0.f, rs1 = 0.f;
#pragma unroll
        for (int nt = 0; nt < 8; ++nt) {
            sc[nt][0] = __expf(sc[nt][0] - mn0); rs0 += sc[nt][0];
            sc[nt][1] = __expf(sc[nt][1] - mn0); rs0 += sc[nt][1];
            sc[nt][2] = __expf(sc[nt][2] - mn1); rs1 += sc[nt][2];
            sc[nt][3] = __expf(sc[nt][3] - mn1); rs1 += sc[nt][3];
        }
        rs0 += __shfl_xor_sync(0xffffffffu, rs0, 1);
        rs0 += __shfl_xor_sync(0xffffffffu, rs0, 2);
        rs1 += __shfl_xor_sync(0xffffffffu, rs1, 1);
        rs1 += __shfl_xor_sync(0xffffffffu, rs1, 2);
        l_[0] = l_[0] * al0 + rs0;
        l_[1] = l_[1] * al1 + rs1;
        m_[0] = mn0;
        m_[1] = mn1;
#pragma unroll
        for (int nt = 0; nt < 8; ++nt) {
            o[nt][0] *= al0; o[nt][1] *= al0;
            o[nt][2] *= al1; o[nt][3] *= al1;
        }

        // ---- O += P V (P repacked in registers; V via ldmatrix.trans) ----
#pragma unroll
        for (int kt = 0; kt < 4; ++kt) {
            uint32_t pah[4], pal[4];
            pah[0] = pk2(sc[2 * kt][0],     sc[2 * kt][1]);
            pah[1] = pk2(sc[2 * kt][2],     sc[2 * kt][3]);
            pah[2] = pk2(sc[2 * kt + 1][0], sc[2 * kt + 1][1]);
            pah[3] = pk2(sc[2 * kt + 1][2], sc[2 * kt + 1][3]);
            pal[0] = pk2(bres(sc[2 * kt][0]),     bres(sc[2 * kt][1]));
            pal[1] = pk2(bres(sc[2 * kt][2]),     bres(sc[2 * kt][3]));
            pal[2] = pk2(bres(sc[2 * kt + 1][0]), bres(sc[2 * kt + 1][1]));
            pal[3] = pk2(bres(sc[2 * kt + 1][2]), bres(sc[2 * kt + 1][3]));
#pragma unroll
            for (int np = 0; np < 4; ++np) {
                const int key = kt * 16 + (lane & 7) + ((lane >> 3) & 1) * 8;
                const int ch  = np * 2 + (lane >> 4);
                const uint32_t ad = sV + fsw(key, ch);
                uint32_t vh4[4], vl4[4];
                LDMX4T(vh4, ad);
                LDMX4T(vl4, ad + (FVL_O - FVH_O));
                uint32_t vb0h[2] = {vh4[0], vh4[1]}, vb1h[2] = {vh4[2], vh4[3]};
                uint32_t vb0l[2] = {vl4[0], vl4[1]}, vb1l[2] = {vl4[2], vl4[3]};
                MMA_BF16(o[np * 2],     pah, vb0h);
                MMA_BF16(o[np * 2],     pah, vb0l);
                MMA_BF16(o[np * 2],     pal, vb0h);
                MMA_BF16(o[np * 2 + 1], pah, vb1h);
                MMA_BF16(o[np * 2 + 1], pah, vb1l);
                MMA_BF16(o[np * 2 + 1], pal, vb1h);
            }
        }

        // Past diagonal: continue only while some row is still fully masked
        if (t >= diag2) {
            int pred = (mn0 <= -1e11f) | (mn1 <= -1e11f);
            if (!__syncthreads_or(pred)) break;
        }
        s_cur = (s_cur == 2) ? 0 : s_cur + 1;
        s_nxt = (s_nxt == 2) ? 0 : s_nxt + 1;
    }

    // ---- normalize + store as bf16 hi/lo for the output projection ----
    const float inv0 = 1.0f / l_[0];
    const float inv1 = 1.0f / l_[1];
    const int gr0 = b * S + q0 + m0 + (lane >> 2);
#pragma unroll
    for (int nt = 0; nt < 8; ++nt) {
        const int col = hc + nt * 8 + (lane & 3) * 2;
        const float a0 = o[nt][0] * inv0, a1 = o[nt][1] * inv0;
        const float a2 = o[nt][2] * inv1, a3 = o[nt][3] * inv1;
        *(uint32_t*)&g_ath[(size_t)gr0 * NN + col]       = pk2(a0, a1);
        *(uint32_t*)&g_atl[(size_t)gr0 * NN + col]       = pk2(bres(a0), bres(a1));
        *(uint32_t*)&g_ath[(size_t)(gr0 + 8) * NN + col] = pk2(a2, a3);
        *(uint32_t*)&g_atl[(size_t)(gr0 + 8) * NN + col] = pk2(bres(a2), bres(a3));
    }
}

// ---------------------------------------------------------------------------
extern "C" void kernel_launch(void* const* d_in, const int* in_sizes, int n_in,
                              void* d_out, int out_size)
{
    (void)in_sizes; (void)n_in; (void)out_size;
    const float* q     = (const float*)d_in[0];
    const float* k     = (const float*)d_in[1];
    const float* v     = (const float*)d_in[2];
    const int*   vmask = (const int*)  d_in[3];
    const int*   qmask = (const int*)  d_in[4];
    const float* Wq = (const float*)d_in[6];
    const float* bq = (const float*)d_in[7];
    const float* Wk = (const float*)d_in[8];
    const float* bk = (const float*)d_in[9];
    const float* Wv = (const float*)d_in[10];
    const float* bv = (const float*)d_in[11];
    const float* Wo = (const float*)d_in[12];
    const float* bo = (const float*)d_in[13];
    float* out = (float*)d_out;

    // Capture-legal (no allocation, no enqueue); idempotent per call.
    cudaFuncSetAttribute(qkv_v4,
        cudaFuncAttributeMaxDynamicSharedMemorySize, GEMM_DSMEM);
    cudaFuncSetAttribute(out_v4,
        cudaFuncAttributeMaxDynamicSharedMemorySize, GEMM_DSMEM);
    cudaFuncSetAttribute(flash_v4,
        cudaFuncAttributeMaxDynamicSharedMemorySize, FLASH_DSMEM);

    conv_all<<<dim3(1024, 1, 7), 256>>>(q, k, v, Wq, Wk, Wv, Wo);
    qkv_v4<<<dim3(NN / BN, M / BM, 3), 256, GEMM_DSMEM>>>(bq, bk, bv);
    flash_v4<<<dim3(S / 128, B * H), 256, FLASH_DSMEM>>>(vmask);
    out_v4<<<dim3(NN / BN, M / BM), 256, GEMM_DSMEM>>>(bo, out, qmask);
}